// round 1
// baseline (speedup 1.0000x reference)
#include <cuda_runtime.h>
#include <math.h>

#define NB    2048
#define NE    30
#define NA    38
#define NN    8
#define BASIS 32
#define KD    64
#define ED    128
#define HK    45
#define HO    91
#define NL    3

// Scratch (device globals; no allocation allowed)
__device__ float g_xs [NB * NE * ED];   // 31.5 MB
__device__ float g_zs [NB * NA * KD];   // 19.9 MB
__device__ float g_msg[NB * NE * KD];   // 15.7 MB

__device__ __forceinline__ float ssp(float x) {
    // softplus(x) - log(2), numerically stable
    return fmaxf(x, 0.f) + log1pf(__expf(-fabsf(x))) - 0.69314718055994530942f;
}

// ---------------------------------------------------------------------------
// Init: xs = broadcast(embedding_elec); zs nuclear part = embedding_nuc
// ---------------------------------------------------------------------------
__global__ void k_init(const float* __restrict__ emb_elec,
                       const float* __restrict__ emb_nuc) {
    const int total_xs  = NB * NE * ED;
    const int total_nuc = NB * NN * KD;
    for (int idx = blockIdx.x * blockDim.x + threadIdx.x; idx < total_xs;
         idx += gridDim.x * blockDim.x) {
        int d = idx % ED;
        int i = (idx / ED) % NE;
        g_xs[idx] = emb_elec[i * ED + d];
    }
    for (int idx = blockIdx.x * blockDim.x + threadIdx.x; idx < total_nuc;
         idx += gridDim.x * blockDim.x) {
        int d = idx % KD;
        int n = (idx / KD) % NN;
        int b = idx / (KD * NN);
        g_zs[(b * NA + NE + n) * KD + d] = emb_nuc[n * KD + d];
    }
}

// ---------------------------------------------------------------------------
// zs (electron part): zs[b, i, :] = xs[b, i, :] @ embed_in_w[l]
// ---------------------------------------------------------------------------
__global__ void __launch_bounds__(256) k_zs(const float* __restrict__ eiw, int l) {
    __shared__ float sW[ED * KD];     // 32 KB
    __shared__ float sx[NE * ED];     // 15 KB
    const int b = blockIdx.x, tid = threadIdx.x;
    const float* W = eiw + (size_t)l * ED * KD;
    for (int idx = tid; idx < ED * KD; idx += 256) sW[idx] = W[idx];
    for (int idx = tid; idx < NE * ED; idx += 256) sx[idx] = g_xs[(size_t)b * NE * ED + idx];
    __syncthreads();
    for (int idx = tid; idx < NE * KD; idx += 256) {
        int i = idx / KD, d = idx % KD;
        float acc = 0.f;
        #pragma unroll
        for (int q = 0; q < ED; ++q) acc = fmaf(sx[i * ED + q], sW[q * KD + d], acc);
        g_zs[((size_t)b * NA + i) * KD + d] = acc;
    }
}

// ---------------------------------------------------------------------------
// msg: for each (b,i): sum_j  ( ssp(db[b,i,j]@w1 + b1) @ w2 + b2 ) * zs[b,j]
// Block = one b (256 threads = 8 warps). Warp owns electrons i = w, w+8, ...
// Lane owns output channels d = lane and d = lane+32 (float2-packed weights).
// ---------------------------------------------------------------------------
__global__ void __launch_bounds__(256) k_msg(const float* __restrict__ dists,
                                             const float* __restrict__ kw1,
                                             const float* __restrict__ kb1,
                                             const float* __restrict__ kw2,
                                             const float* __restrict__ kb2, int l) {
    __shared__ float2 s_w1v[BASIS * 32];  // [q][c] -> (w1[q][c], w1[q][c+32] or 0)
    __shared__ float  s_b1[64];           // padded, zeros past HK
    __shared__ float2 s_w2v[HK * 32];     // [k][c] -> (w2[k][c], w2[k][c+32])
    __shared__ float2 s_b2v[32];
    __shared__ float2 s_zsv[NA * 32];     // [j][c]
    __shared__ float  s_db[8][32];
    __shared__ float  s_h[8][48];

    const int b = blockIdx.x, tid = threadIdx.x;
    const int w = tid >> 5, lane = tid & 31;
    const float* w1 = kw1 + (size_t)l * BASIS * HK;
    const float* b1 = kb1 + (size_t)l * HK;
    const float* w2 = kw2 + (size_t)l * HK * KD;
    const float* b2 = kb2 + (size_t)l * KD;

    for (int idx = tid; idx < BASIS * 32; idx += 256) {
        int q = idx >> 5, c = idx & 31;
        float x = w1[q * HK + c];
        float y = (c < HK - 32) ? w1[q * HK + c + 32] : 0.f;
        s_w1v[idx] = make_float2(x, y);
    }
    for (int idx = tid; idx < 64; idx += 256) s_b1[idx] = (idx < HK) ? b1[idx] : 0.f;
    for (int idx = tid; idx < HK * 32; idx += 256) {
        int k = idx >> 5, c = idx & 31;
        s_w2v[idx] = make_float2(w2[k * KD + c], w2[k * KD + c + 32]);
    }
    if (tid < 32) s_b2v[tid] = make_float2(b2[tid], b2[tid + 32]);
    for (int idx = tid; idx < NA * 32; idx += 256) {
        int j = idx >> 5, c = idx & 31;
        const float* z = g_zs + ((size_t)b * NA + j) * KD;
        s_zsv[idx] = make_float2(z[c], z[c + 32]);
    }
    __syncthreads();

    for (int i = w; i < NE; i += 8) {
        float m0 = 0.f, m1 = 0.f;
        const float* dbase = dists + ((size_t)(b * NE + i)) * NA * BASIS;
        for (int j = 0; j < NA; ++j) {
            if (j == i) continue;
            s_db[w][lane] = dbase[j * BASIS + lane];
            __syncwarp();
            float a0 = s_b1[lane];
            float a1 = s_b1[32 + lane];
            #pragma unroll
            for (int q = 0; q < BASIS; ++q) {
                float dv = s_db[w][q];
                float2 wv = s_w1v[q * 32 + lane];
                a0 = fmaf(dv, wv.x, a0);
                a1 = fmaf(dv, wv.y, a1);
            }
            s_h[w][lane] = ssp(a0);
            if (lane < HK - 32) s_h[w][32 + lane] = ssp(a1);
            __syncwarp();
            float2 bv = s_b2v[lane];
            float acc0 = bv.x, acc1 = bv.y;
            #pragma unroll
            for (int k = 0; k < HK; ++k) {
                float h = s_h[w][k];
                float2 wv = s_w2v[k * 32 + lane];
                acc0 = fmaf(h, wv.x, acc0);
                acc1 = fmaf(h, wv.y, acc1);
            }
            float2 z = s_zsv[j * 32 + lane];
            m0 = fmaf(acc0, z.x, m0);
            m1 = fmaf(acc1, z.y, m1);
            __syncwarp();
        }
        float* mp = g_msg + ((size_t)(b * NE + i)) * KD;
        mp[lane] = m0;
        mp[32 + lane] = m1;
    }
}

// ---------------------------------------------------------------------------
// out MLP + residual: xs_out = xs + ssp(msg@W1 + b1)@W2 + b2
// Block = one b, warp per electron; lane owns d, d+32, d+64, d+96.
// ---------------------------------------------------------------------------
#define V_SW1_OFF 0
#define V_SB1_OFF 5840
#define V_SW2_OFF 5936
#define V_SB2_OFF 17584
#define V_MSG_OFF 17712
#define V_SH_OFF  19632
#define V_SMEM_FLOATS (19632 + 8 * 92)
#define V_SMEM_BYTES  (V_SMEM_FLOATS * 4)

__global__ void __launch_bounds__(256) k_out(const float* __restrict__ ow1,
                                             const float* __restrict__ ob1,
                                             const float* __restrict__ ow2,
                                             const float* __restrict__ ob2,
                                             int l, float* __restrict__ xs_out) {
    extern __shared__ float sm[];
    float* sw1  = sm + V_SW1_OFF;   // 64*91 + pad
    float* sb1  = sm + V_SB1_OFF;   // 96 (padded)
    float* sw2  = sm + V_SW2_OFF;   // 91*128
    float* sb2  = sm + V_SB2_OFF;   // 128
    float* smsg = sm + V_MSG_OFF;   // 30*64
    float* sh   = sm + V_SH_OFF;    // 8*92

    const int b = blockIdx.x, tid = threadIdx.x;
    const int w = tid >> 5, lane = tid & 31;
    const float* W1 = ow1 + (size_t)l * KD * HO;
    const float* B1 = ob1 + (size_t)l * HO;
    const float* W2 = ow2 + (size_t)l * HO * ED;
    const float* B2 = ob2 + (size_t)l * ED;

    for (int idx = tid; idx < 5840; idx += 256) sw1[idx] = (idx < KD * HO) ? W1[idx] : 0.f;
    for (int idx = tid; idx < 96; idx += 256)   sb1[idx] = (idx < HO) ? B1[idx] : 0.f;
    for (int idx = tid; idx < HO * ED; idx += 256) sw2[idx] = W2[idx];
    for (int idx = tid; idx < ED; idx += 256)   sb2[idx] = B2[idx];
    for (int idx = tid; idx < NE * KD; idx += 256) smsg[idx] = g_msg[(size_t)b * NE * KD + idx];
    __syncthreads();

    for (int i = w; i < NE; i += 8) {
        float a0 = sb1[lane], a1 = sb1[lane + 32], a2 = sb1[lane + 64];
        const float* mrow = smsg + i * KD;
        #pragma unroll
        for (int q = 0; q < KD; ++q) {
            float mq = mrow[q];
            a0 = fmaf(mq, sw1[q * HO + lane], a0);
            a1 = fmaf(mq, sw1[q * HO + lane + 32], a1);
            a2 = fmaf(mq, sw1[q * HO + lane + 64], a2);   // lanes >= 27 read pad, discarded
        }
        sh[w * 92 + lane]      = ssp(a0);
        sh[w * 92 + lane + 32] = ssp(a1);
        if (lane < HO - 64) sh[w * 92 + lane + 64] = ssp(a2);
        __syncwarp();
        float c0 = sb2[lane], c1 = sb2[lane + 32], c2 = sb2[lane + 64], c3 = sb2[lane + 96];
        #pragma unroll
        for (int k = 0; k < HO; ++k) {
            float h = sh[w * 92 + k];
            c0 = fmaf(h, sw2[k * ED + lane],      c0);
            c1 = fmaf(h, sw2[k * ED + lane + 32], c1);
            c2 = fmaf(h, sw2[k * ED + lane + 64], c2);
            c3 = fmaf(h, sw2[k * ED + lane + 96], c3);
        }
        size_t base = ((size_t)(b * NE + i)) * ED;
        xs_out[base + lane]      = g_xs[base + lane]      + c0;
        xs_out[base + lane + 32] = g_xs[base + lane + 32] + c1;
        xs_out[base + lane + 64] = g_xs[base + lane + 64] + c2;
        xs_out[base + lane + 96] = g_xs[base + lane + 96] + c3;
        __syncwarp();
    }
}

// ---------------------------------------------------------------------------
extern "C" void kernel_launch(void* const* d_in, const int* in_sizes, int n_in,
                              void* d_out, int out_size) {
    const float* dists    = (const float*)d_in[0];
    const float* emb_elec = (const float*)d_in[1];
    const float* emb_nuc  = (const float*)d_in[2];
    const float* kw1      = (const float*)d_in[3];
    const float* kb1      = (const float*)d_in[4];
    const float* kw2      = (const float*)d_in[5];
    const float* kb2      = (const float*)d_in[6];
    const float* eiw      = (const float*)d_in[7];
    const float* ow1      = (const float*)d_in[8];
    const float* ob1      = (const float*)d_in[9];
    const float* ow2      = (const float*)d_in[10];
    const float* ob2      = (const float*)d_in[11];
    float* out = (float*)d_out;

    cudaFuncSetAttribute(k_out, cudaFuncAttributeMaxDynamicSharedMemorySize, V_SMEM_BYTES);

    void* xsptr = nullptr;
    cudaGetSymbolAddress(&xsptr, g_xs);

    k_init<<<4096, 256>>>(emb_elec, emb_nuc);
    for (int l = 0; l < NL; ++l) {
        k_zs<<<NB, 256>>>(eiw, l);
        k_msg<<<NB, 256>>>(dists, kw1, kb1, kw2, kb2, l);
        float* xs_out = (l == NL - 1) ? out : (float*)xsptr;
        k_out<<<NB, 256, V_SMEM_BYTES>>>(ow1, ob1, ow2, ob2, l, xs_out);
    }
}

// round 2
// speedup vs baseline: 1.0008x; 1.0008x over previous
#include <cuda_runtime.h>
#include <math.h>

#define NB    2048
#define NE    30
#define NA    38
#define NN    8
#define BASIS 32
#define KD    64
#define ED    128
#define HK    45
#define HO    91
#define NL    3

// Scratch (device globals; no allocation allowed)
__device__ float g_xs [NB * NE * ED];   // 31.5 MB
__device__ float g_zs [NB * NA * KD];   // 19.9 MB
__device__ float g_msg[NB * NE * KD];   // 15.7 MB

__device__ __forceinline__ float ssp(float x) {
    // softplus(x) - log(2), numerically stable
    return fmaxf(x, 0.f) + log1pf(__expf(-fabsf(x))) - 0.69314718055994530942f;
}

// ---------------------------------------------------------------------------
// Init: xs = broadcast(embedding_elec); zs nuclear part = embedding_nuc
// ---------------------------------------------------------------------------
__global__ void k_init(const float* __restrict__ emb_elec,
                       const float* __restrict__ emb_nuc) {
    const int total_xs  = NB * NE * ED;
    const int total_nuc = NB * NN * KD;
    for (int idx = blockIdx.x * blockDim.x + threadIdx.x; idx < total_xs;
         idx += gridDim.x * blockDim.x) {
        int d = idx % ED;
        int i = (idx / ED) % NE;
        g_xs[idx] = emb_elec[i * ED + d];
    }
    for (int idx = blockIdx.x * blockDim.x + threadIdx.x; idx < total_nuc;
         idx += gridDim.x * blockDim.x) {
        int d = idx % KD;
        int n = (idx / KD) % NN;
        int b = idx / (KD * NN);
        g_zs[(b * NA + NE + n) * KD + d] = emb_nuc[n * KD + d];
    }
}

// ---------------------------------------------------------------------------
// zs (electron part): zs[b, i, :] = xs[b, i, :] @ embed_in_w[l]
// ---------------------------------------------------------------------------
__global__ void __launch_bounds__(256) k_zs(const float* __restrict__ eiw, int l) {
    __shared__ float sW[ED * KD];     // 32 KB
    __shared__ float sx[NE * ED];     // 15 KB
    const int b = blockIdx.x, tid = threadIdx.x;
    const float* W = eiw + (size_t)l * ED * KD;
    for (int idx = tid; idx < ED * KD; idx += 256) sW[idx] = W[idx];
    for (int idx = tid; idx < NE * ED; idx += 256) sx[idx] = g_xs[(size_t)b * NE * ED + idx];
    __syncthreads();
    for (int idx = tid; idx < NE * KD; idx += 256) {
        int i = idx / KD, d = idx % KD;
        float acc = 0.f;
        #pragma unroll
        for (int q = 0; q < ED; ++q) acc = fmaf(sx[i * ED + q], sW[q * KD + d], acc);
        g_zs[((size_t)b * NA + i) * KD + d] = acc;
    }
}

// ---------------------------------------------------------------------------
// msg: for each (b,i): sum_j  ( ssp(db[b,i,j]@w1 + b1) @ w2 + b2 ) * zs[b,j]
// Block = one b (256 threads = 8 warps). Warp owns electrons i = w, w+8, ...
// Lane owns output channels d = lane and d = lane+32 (float2-packed weights).
// ---------------------------------------------------------------------------
__global__ void __launch_bounds__(256) k_msg(const float* __restrict__ dists,
                                             const float* __restrict__ kw1,
                                             const float* __restrict__ kb1,
                                             const float* __restrict__ kw2,
                                             const float* __restrict__ kb2, int l) {
    __shared__ float2 s_w1v[BASIS * 32];  // [q][c] -> (w1[q][c], w1[q][c+32] or 0)
    __shared__ float  s_b1[64];           // padded, zeros past HK
    __shared__ float2 s_w2v[HK * 32];     // [k][c] -> (w2[k][c], w2[k][c+32])
    __shared__ float2 s_b2v[32];
    __shared__ float2 s_zsv[NA * 32];     // [j][c]
    __shared__ float  s_db[8][32];
    __shared__ float  s_h[8][48];

    const int b = blockIdx.x, tid = threadIdx.x;
    const int w = tid >> 5, lane = tid & 31;
    const float* w1 = kw1 + (size_t)l * BASIS * HK;
    const float* b1 = kb1 + (size_t)l * HK;
    const float* w2 = kw2 + (size_t)l * HK * KD;
    const float* b2 = kb2 + (size_t)l * KD;

    for (int idx = tid; idx < BASIS * 32; idx += 256) {
        int q = idx >> 5, c = idx & 31;
        float x = w1[q * HK + c];
        float y = (c < HK - 32) ? w1[q * HK + c + 32] : 0.f;
        s_w1v[idx] = make_float2(x, y);
    }
    for (int idx = tid; idx < 64; idx += 256) s_b1[idx] = (idx < HK) ? b1[idx] : 0.f;
    for (int idx = tid; idx < HK * 32; idx += 256) {
        int k = idx >> 5, c = idx & 31;
        s_w2v[idx] = make_float2(w2[k * KD + c], w2[k * KD + c + 32]);
    }
    if (tid < 32) s_b2v[tid] = make_float2(b2[tid], b2[tid + 32]);
    for (int idx = tid; idx < NA * 32; idx += 256) {
        int j = idx >> 5, c = idx & 31;
        const float* z = g_zs + ((size_t)b * NA + j) * KD;
        s_zsv[idx] = make_float2(z[c], z[c + 32]);
    }
    __syncthreads();

    for (int i = w; i < NE; i += 8) {
        float m0 = 0.f, m1 = 0.f;
        const float* dbase = dists + ((size_t)(b * NE + i)) * NA * BASIS;
        for (int j = 0; j < NA; ++j) {
            if (j == i) continue;
            s_db[w][lane] = dbase[j * BASIS + lane];
            __syncwarp();
            float a0 = s_b1[lane];
            float a1 = s_b1[32 + lane];
            #pragma unroll
            for (int q = 0; q < BASIS; ++q) {
                float dv = s_db[w][q];
                float2 wv = s_w1v[q * 32 + lane];
                a0 = fmaf(dv, wv.x, a0);
                a1 = fmaf(dv, wv.y, a1);
            }
            s_h[w][lane] = ssp(a0);
            if (lane < HK - 32) s_h[w][32 + lane] = ssp(a1);
            __syncwarp();
            float2 bv = s_b2v[lane];
            float acc0 = bv.x, acc1 = bv.y;
            #pragma unroll
            for (int k = 0; k < HK; ++k) {
                float h = s_h[w][k];
                float2 wv = s_w2v[k * 32 + lane];
                acc0 = fmaf(h, wv.x, acc0);
                acc1 = fmaf(h, wv.y, acc1);
            }
            float2 z = s_zsv[j * 32 + lane];
            m0 = fmaf(acc0, z.x, m0);
            m1 = fmaf(acc1, z.y, m1);
            __syncwarp();
        }
        float* mp = g_msg + ((size_t)(b * NE + i)) * KD;
        mp[lane] = m0;
        mp[32 + lane] = m1;
    }
}

// ---------------------------------------------------------------------------
// out MLP + residual: xs_out = xs + ssp(msg@W1 + b1)@W2 + b2
// Block = one b, warp per electron; lane owns d, d+32, d+64, d+96.
// ---------------------------------------------------------------------------
#define V_SW1_OFF 0
#define V_SB1_OFF 5840
#define V_SW2_OFF 5936
#define V_SB2_OFF 17584
#define V_MSG_OFF 17712
#define V_SH_OFF  19632
#define V_SMEM_FLOATS (19632 + 8 * 92)
#define V_SMEM_BYTES  (V_SMEM_FLOATS * 4)

__global__ void __launch_bounds__(256) k_out(const float* __restrict__ ow1,
                                             const float* __restrict__ ob1,
                                             const float* __restrict__ ow2,
                                             const float* __restrict__ ob2,
                                             int l, float* __restrict__ xs_out) {
    extern __shared__ float sm[];
    float* sw1  = sm + V_SW1_OFF;   // 64*91 + pad
    float* sb1  = sm + V_SB1_OFF;   // 96 (padded)
    float* sw2  = sm + V_SW2_OFF;   // 91*128
    float* sb2  = sm + V_SB2_OFF;   // 128
    float* smsg = sm + V_MSG_OFF;   // 30*64
    float* sh   = sm + V_SH_OFF;    // 8*92

    const int b = blockIdx.x, tid = threadIdx.x;
    const int w = tid >> 5, lane = tid & 31;
    const float* W1 = ow1 + (size_t)l * KD * HO;
    const float* B1 = ob1 + (size_t)l * HO;
    const float* W2 = ow2 + (size_t)l * HO * ED;
    const float* B2 = ob2 + (size_t)l * ED;

    for (int idx = tid; idx < 5840; idx += 256) sw1[idx] = (idx < KD * HO) ? W1[idx] : 0.f;
    for (int idx = tid; idx < 96; idx += 256)   sb1[idx] = (idx < HO) ? B1[idx] : 0.f;
    for (int idx = tid; idx < HO * ED; idx += 256) sw2[idx] = W2[idx];
    for (int idx = tid; idx < ED; idx += 256)   sb2[idx] = B2[idx];
    for (int idx = tid; idx < NE * KD; idx += 256) smsg[idx] = g_msg[(size_t)b * NE * KD + idx];
    __syncthreads();

    for (int i = w; i < NE; i += 8) {
        float a0 = sb1[lane], a1 = sb1[lane + 32], a2 = sb1[lane + 64];
        const float* mrow = smsg + i * KD;
        #pragma unroll
        for (int q = 0; q < KD; ++q) {
            float mq = mrow[q];
            a0 = fmaf(mq, sw1[q * HO + lane], a0);
            a1 = fmaf(mq, sw1[q * HO + lane + 32], a1);
            a2 = fmaf(mq, sw1[q * HO + lane + 64], a2);   // lanes >= 27 read pad, discarded
        }
        sh[w * 92 + lane]      = ssp(a0);
        sh[w * 92 + lane + 32] = ssp(a1);
        if (lane < HO - 64) sh[w * 92 + lane + 64] = ssp(a2);
        __syncwarp();
        float c0 = sb2[lane], c1 = sb2[lane + 32], c2 = sb2[lane + 64], c3 = sb2[lane + 96];
        #pragma unroll
        for (int k = 0; k < HO; ++k) {
            float h = sh[w * 92 + k];
            c0 = fmaf(h, sw2[k * ED + lane],      c0);
            c1 = fmaf(h, sw2[k * ED + lane + 32], c1);
            c2 = fmaf(h, sw2[k * ED + lane + 64], c2);
            c3 = fmaf(h, sw2[k * ED + lane + 96], c3);
        }
        size_t base = ((size_t)(b * NE + i)) * ED;
        xs_out[base + lane]      = g_xs[base + lane]      + c0;
        xs_out[base + lane + 32] = g_xs[base + lane + 32] + c1;
        xs_out[base + lane + 64] = g_xs[base + lane + 64] + c2;
        xs_out[base + lane + 96] = g_xs[base + lane + 96] + c3;
        __syncwarp();
    }
}

// ---------------------------------------------------------------------------
extern "C" void kernel_launch(void* const* d_in, const int* in_sizes, int n_in,
                              void* d_out, int out_size) {
    const float* dists    = (const float*)d_in[0];
    const float* emb_elec = (const float*)d_in[1];
    const float* emb_nuc  = (const float*)d_in[2];
    const float* kw1      = (const float*)d_in[3];
    const float* kb1      = (const float*)d_in[4];
    const float* kw2      = (const float*)d_in[5];
    const float* kb2      = (const float*)d_in[6];
    const float* eiw      = (const float*)d_in[7];
    const float* ow1      = (const float*)d_in[8];
    const float* ob1      = (const float*)d_in[9];
    const float* ow2      = (const float*)d_in[10];
    const float* ob2      = (const float*)d_in[11];
    float* out = (float*)d_out;

    cudaFuncSetAttribute(k_out, cudaFuncAttributeMaxDynamicSharedMemorySize, V_SMEM_BYTES);

    void* xsptr = nullptr;
    cudaGetSymbolAddress(&xsptr, g_xs);

    k_init<<<4096, 256>>>(emb_elec, emb_nuc);
    for (int l = 0; l < NL; ++l) {
        k_zs<<<NB, 256>>>(eiw, l);
        k_msg<<<NB, 256>>>(dists, kw1, kb1, kw2, kb2, l);
        float* xs_out = (l == NL - 1) ? out : (float*)xsptr;
        k_out<<<NB, 256, V_SMEM_BYTES>>>(ow1, ob1, ow2, ob2, l, xs_out);
    }
}

// round 3
// speedup vs baseline: 1.8003x; 1.7988x over previous
#include <cuda_runtime.h>
#include <math.h>

#define NB    2048
#define NE    30
#define NA    38
#define NN    8
#define BASIS 32
#define KD    64
#define ED    128
#define HK    45
#define HKP   48
#define HO    91
#define NL    3

typedef unsigned long long ull;

__device__ float g_xs [NB * NE * ED];
__device__ float g_msg[NB * NE * KD];

__device__ __forceinline__ float ssp(float x) {
    float t = __expf(-fabsf(x));
    return fmaxf(x, 0.f) + __logf(1.f + t) - 0.69314718055994530942f;
}
__device__ __forceinline__ ull ffma2(ull a, ull b, ull c) {
    ull d; asm("fma.rn.f32x2 %0, %1, %2, %3;" : "=l"(d) : "l"(a), "l"(b), "l"(c));
    return d;
}
__device__ __forceinline__ ull pack2(float x, float y) {
    ull r; asm("mov.b64 %0, {%1, %2};" : "=l"(r) : "f"(x), "f"(y)); return r;
}
__device__ __forceinline__ float2 unpack2(ull v) {
    float2 r; asm("mov.b64 {%0, %1}, %2;" : "=f"(r.x), "=f"(r.y) : "l"(v)); return r;
}
__device__ __forceinline__ ull ldsu64(const float2* p) {
    return *reinterpret_cast<const ull*>(p);
}

__global__ void k_init(const float* __restrict__ emb_elec) {
    const int total = NB * NE * ED;
    for (int idx = blockIdx.x * blockDim.x + threadIdx.x; idx < total;
         idx += gridDim.x * blockDim.x) {
        int d = idx % ED, i = (idx / ED) % NE;
        g_xs[idx] = emb_elec[i * ED + d];
    }
}

// ---------------------------------------------------------------------------
// k_msg: per block b: zs into smem, then pair MLP (4 j's per sweep, f32x2)
// smem floats: [0..2560) zs2 (20 jp x 64ch float2); [2560..) overlay:
//   phase1: eiw 8192
//   phase2: w1 2048 @2560 | w2(48x64) 3072 @4608 | db 1024 @7680 | h 1536 @8704
// ---------------------------------------------------------------------------
__global__ void __launch_bounds__(256) k_msg(const float* __restrict__ dists,
                                             const float* __restrict__ emb_nuc,
                                             const float* __restrict__ eiw,
                                             const float* __restrict__ kw1,
                                             const float* __restrict__ kb1,
                                             const float* __restrict__ kw2,
                                             const float* __restrict__ kb2, int l) {
    __shared__ float sm[10752];
    float2* s_zs2 = reinterpret_cast<float2*>(sm);          // [jp*64 + c]
    float*  s_eiw = sm + 2560;
    float*  s_w1  = sm + 2560;                               // [q*64 + c]
    float*  s_w2  = sm + 4608;                               // [k*64 + c], 48 rows
    float2* s_dbw = reinterpret_cast<float2*>(sm + 7680);    // warp w: +w*64
    float2* s_hw  = reinterpret_cast<float2*>(sm + 8704);    // warp w: +w*96

    const int b = blockIdx.x, tid = threadIdx.x;
    const int w = tid >> 5, lane = tid & 31;
    float* zf = sm;  // component-wise writes into zs2

    // phase 1a: eiw overlay + nuclear zs + padding
    {
        const float* W = eiw + (size_t)l * ED * KD;
        for (int idx = tid; idx < ED * KD; idx += 256) s_eiw[idx] = W[idx];
        for (int idx = tid; idx < NN * KD; idx += 256) {
            int n = idx >> 6, c = idx & 63;
            int jp = (NE + n) >> 1, comp = n & 1;
            zf[(jp * 64 + c) * 2 + comp] = emb_nuc[n * KD + c];
        }
        if (tid < 128) zf[19 * 128 + tid] = 0.f;   // jp=19 (j=38,39) zero
    }
    __syncthreads();

    // phase 1b: electron zs2 = xs @ eiw
    for (int t = w; t < 2 * NE; t += 8) {
        int i = t >> 1, c = (t & 1) * 32 + lane;
        const float* xr = g_xs + ((size_t)(b * NE + i)) * ED;
        float acc = 0.f;
        #pragma unroll 8
        for (int q = 0; q < ED; ++q) acc = fmaf(__ldg(xr + q), s_eiw[q * 64 + c], acc);
        zf[((i >> 1) * 64 + c) * 2 + (i & 1)] = acc;
    }
    __syncthreads();

    // phase 2a: pair-MLP weights (w1 zero-padded cols>=45, w2 zero rows>=45)
    {
        const float* w1 = kw1 + (size_t)l * BASIS * HK;
        const float* w2 = kw2 + (size_t)l * HK * KD;
        for (int idx = tid; idx < BASIS * 64; idx += 256) {
            int q = idx >> 6, c = idx & 63;
            s_w1[idx] = (c < HK) ? w1[q * HK + c] : 0.f;
        }
        for (int idx = tid; idx < HKP * 64; idx += 256) {
            int k = idx >> 6, c = idx & 63;
            s_w2[idx] = (k < HK) ? w2[k * KD + c] : 0.f;
        }
    }
    __syncthreads();

    const float* b1 = kb1 + (size_t)l * HK;
    const float* b2 = kb2 + (size_t)l * KD;
    float b1x = b1[lane];
    float b1y = (lane + 32 < HK) ? b1[lane + 32] : 0.f;
    const ull db1x = pack2(b1x, b1x), db1y = pack2(b1y, b1y);
    float b2x = b2[lane], b2y = b2[lane + 32];
    const ull db2x = pack2(b2x, b2x), db2y = pack2(b2y, b2y);

    float2* db01 = s_dbw + w * 64;
    float2* db23 = db01 + 32;
    float2* h01  = s_hw + w * 96;
    float2* h23  = h01 + 48;

    for (int i = w; i < NE; i += 8) {
        const float* dbase = dists + ((size_t)(b * NE + i)) * NA * BASIS;
        ull m01x = 0, m23x = 0, m01y = 0, m23y = 0;

        for (int jg = 0; jg < 10; ++jg) {
            const int j0 = jg * 4;
            // stage db rows j0..j0+3 (rows >= NA zeroed)
            float v0 = dbase[(j0 + 0) * BASIS + lane];
            float v1 = dbase[(j0 + 1) * BASIS + lane];
            float v2 = (j0 + 2 < NA) ? dbase[(j0 + 2) * BASIS + lane] : 0.f;
            float v3 = (j0 + 3 < NA) ? dbase[(j0 + 3) * BASIS + lane] : 0.f;
            db01[lane] = make_float2(v0, v1);
            db23[lane] = make_float2(v2, v3);
            __syncwarp();

            // GEMM1: a = db @ w1 + b1
            ull a01x = db1x, a23x = db1x, a01y = db1y, a23y = db1y;
            #pragma unroll
            for (int q = 0; q < BASIS; ++q) {
                ull d01 = ldsu64(db01 + q);
                ull d23 = ldsu64(db23 + q);
                float wx = s_w1[q * 64 + lane];
                float wy = s_w1[q * 64 + 32 + lane];
                ull wxx = pack2(wx, wx), wyy = pack2(wy, wy);
                a01x = ffma2(d01, wxx, a01x);
                a23x = ffma2(d23, wxx, a23x);
                a01y = ffma2(d01, wyy, a01y);
                a23y = ffma2(d23, wyy, a23y);
            }
            // ssp -> h
            {
                float2 t;
                t = unpack2(a01x); h01[lane] = make_float2(ssp(t.x), ssp(t.y));
                t = unpack2(a23x); h23[lane] = make_float2(ssp(t.x), ssp(t.y));
                if (lane < HKP - 32) {
                    t = unpack2(a01y); h01[lane + 32] = make_float2(ssp(t.x), ssp(t.y));
                    t = unpack2(a23y); h23[lane + 32] = make_float2(ssp(t.x), ssp(t.y));
                }
            }
            __syncwarp();

            // GEMM2: Ws = h @ w2 + b2
            ull c01x = db2x, c23x = db2x, c01y = db2y, c23y = db2y;
            #pragma unroll
            for (int k = 0; k < HKP; ++k) {
                ull hh01 = ldsu64(h01 + k);
                ull hh23 = ldsu64(h23 + k);
                float wx = s_w2[k * 64 + lane];
                float wy = s_w2[k * 64 + 32 + lane];
                ull wxx = pack2(wx, wx), wyy = pack2(wy, wy);
                c01x = ffma2(hh01, wxx, c01x);
                c23x = ffma2(hh23, wxx, c23x);
                c01y = ffma2(hh01, wyy, c01y);
                c23y = ffma2(hh23, wyy, c23y);
            }

            // msg += Ws * zs[j]  (mask j==i and j>=NA; jp=19 already zero)
            float2 z01x = s_zs2[(2 * jg) * 64 + lane];
            float2 z01y = s_zs2[(2 * jg) * 64 + lane + 32];
            float2 z23x = s_zs2[(2 * jg + 1) * 64 + lane];
            float2 z23y = s_zs2[(2 * jg + 1) * 64 + lane + 32];
            if (j0 == i)     { z01x.x = 0.f; z01y.x = 0.f; }
            if (j0 + 1 == i) { z01x.y = 0.f; z01y.y = 0.f; }
            if (j0 + 2 == i) { z23x.x = 0.f; z23y.x = 0.f; }
            if (j0 + 3 == i) { z23x.y = 0.f; z23y.y = 0.f; }
            m01x = ffma2(c01x, pack2(z01x.x, z01x.y), m01x);
            m23x = ffma2(c23x, pack2(z23x.x, z23x.y), m23x);
            m01y = ffma2(c01y, pack2(z01y.x, z01y.y), m01y);
            m23y = ffma2(c23y, pack2(z23y.x, z23y.y), m23y);
            __syncwarp();
        }
        float2 u = unpack2(m01x), v = unpack2(m23x);
        float mlo = (u.x + u.y) + (v.x + v.y);
        u = unpack2(m01y); v = unpack2(m23y);
        float mhi = (u.x + u.y) + (v.x + v.y);
        float* mp = g_msg + ((size_t)(b * NE + i)) * KD;
        mp[lane] = mlo;
        mp[lane + 32] = mhi;
    }
}

// ---------------------------------------------------------------------------
// k_out (unchanged from passing R0 kernel)
// ---------------------------------------------------------------------------
#define V_SW1_OFF 0
#define V_SB1_OFF 5840
#define V_SW2_OFF 5936
#define V_SB2_OFF 17584
#define V_MSG_OFF 17712
#define V_SH_OFF  19632
#define V_SMEM_FLOATS (19632 + 8 * 92)
#define V_SMEM_BYTES  (V_SMEM_FLOATS * 4)

__global__ void __launch_bounds__(256) k_out(const float* __restrict__ ow1,
                                             const float* __restrict__ ob1,
                                             const float* __restrict__ ow2,
                                             const float* __restrict__ ob2,
                                             int l, float* __restrict__ xs_out) {
    extern __shared__ float smo[];
    float* sw1  = smo + V_SW1_OFF;
    float* sb1  = smo + V_SB1_OFF;
    float* sw2  = smo + V_SW2_OFF;
    float* sb2  = smo + V_SB2_OFF;
    float* smsg = smo + V_MSG_OFF;
    float* sh   = smo + V_SH_OFF;

    const int b = blockIdx.x, tid = threadIdx.x;
    const int w = tid >> 5, lane = tid & 31;
    const float* W1 = ow1 + (size_t)l * KD * HO;
    const float* B1 = ob1 + (size_t)l * HO;
    const float* W2 = ow2 + (size_t)l * HO * ED;
    const float* B2 = ob2 + (size_t)l * ED;

    for (int idx = tid; idx < 5840; idx += 256) sw1[idx] = (idx < KD * HO) ? W1[idx] : 0.f;
    for (int idx = tid; idx < 96; idx += 256)   sb1[idx] = (idx < HO) ? B1[idx] : 0.f;
    for (int idx = tid; idx < HO * ED; idx += 256) sw2[idx] = W2[idx];
    for (int idx = tid; idx < ED; idx += 256)   sb2[idx] = B2[idx];
    for (int idx = tid; idx < NE * KD; idx += 256) smsg[idx] = g_msg[(size_t)b * NE * KD + idx];
    __syncthreads();

    for (int i = w; i < NE; i += 8) {
        float a0 = sb1[lane], a1 = sb1[lane + 32], a2 = sb1[lane + 64];
        const float* mrow = smsg + i * KD;
        #pragma unroll
        for (int q = 0; q < KD; ++q) {
            float mq = mrow[q];
            a0 = fmaf(mq, sw1[q * HO + lane], a0);
            a1 = fmaf(mq, sw1[q * HO + lane + 32], a1);
            a2 = fmaf(mq, sw1[q * HO + lane + 64], a2);
        }
        sh[w * 92 + lane]      = ssp(a0);
        sh[w * 92 + lane + 32] = ssp(a1);
        if (lane < HO - 64) sh[w * 92 + lane + 64] = ssp(a2);
        __syncwarp();
        float c0 = sb2[lane], c1 = sb2[lane + 32], c2 = sb2[lane + 64], c3 = sb2[lane + 96];
        #pragma unroll
        for (int k = 0; k < HO; ++k) {
            float h = sh[w * 92 + k];
            c0 = fmaf(h, sw2[k * ED + lane],      c0);
            c1 = fmaf(h, sw2[k * ED + lane + 32], c1);
            c2 = fmaf(h, sw2[k * ED + lane + 64], c2);
            c3 = fmaf(h, sw2[k * ED + lane + 96], c3);
        }
        size_t base = ((size_t)(b * NE + i)) * ED;
        xs_out[base + lane]      = g_xs[base + lane]      + c0;
        xs_out[base + lane + 32] = g_xs[base + lane + 32] + c1;
        xs_out[base + lane + 64] = g_xs[base + lane + 64] + c2;
        xs_out[base + lane + 96] = g_xs[base + lane + 96] + c3;
        __syncwarp();
    }
}

// ---------------------------------------------------------------------------
extern "C" void kernel_launch(void* const* d_in, const int* in_sizes, int n_in,
                              void* d_out, int out_size) {
    const float* dists    = (const float*)d_in[0];
    const float* emb_elec = (const float*)d_in[1];
    const float* emb_nuc  = (const float*)d_in[2];
    const float* kw1      = (const float*)d_in[3];
    const float* kb1      = (const float*)d_in[4];
    const float* kw2      = (const float*)d_in[5];
    const float* kb2      = (const float*)d_in[6];
    const float* eiw      = (const float*)d_in[7];
    const float* ow1      = (const float*)d_in[8];
    const float* ob1      = (const float*)d_in[9];
    const float* ow2      = (const float*)d_in[10];
    const float* ob2      = (const float*)d_in[11];
    float* out = (float*)d_out;

    cudaFuncSetAttribute(k_out, cudaFuncAttributeMaxDynamicSharedMemorySize, V_SMEM_BYTES);
    void* xsptr = nullptr;
    cudaGetSymbolAddress(&xsptr, g_xs);

    k_init<<<4096, 256>>>(emb_elec);
    for (int l = 0; l < NL; ++l) {
        k_msg<<<NB, 256>>>(dists, emb_nuc, eiw, kw1, kb1, kw2, kb2, l);
        float* xs_out = (l == NL - 1) ? out : (float*)xsptr;
        k_out<<<NB, 256, V_SMEM_BYTES>>>(ow1, ob1, ow2, ob2, l, xs_out);
    }
}

// round 4
// speedup vs baseline: 2.3676x; 1.3151x over previous
#include <cuda_runtime.h>

#define NB    2048
#define NE    30
#define NA    38
#define NN    8
#define BASIS 32
#define KD    64
#define ED    128
#define HK    45
#define HKP   48
#define HO    91
#define HOP   96
#define NL    3

typedef unsigned long long ull;

__device__ float g_xs [NB * NE * ED];
__device__ float g_msg[NB * NE * KD];

__device__ __forceinline__ float ssp(float x) {
    float t = __expf(-fabsf(x));
    return fmaxf(x, 0.f) + __logf(1.f + t) - 0.69314718055994530942f;
}
__device__ __forceinline__ ull ffma2(ull a, ull b, ull c) {
    ull d; asm("fma.rn.f32x2 %0, %1, %2, %3;" : "=l"(d) : "l"(a), "l"(b), "l"(c));
    return d;
}
__device__ __forceinline__ ull pack2(float x, float y) {
    ull r; asm("mov.b64 %0, {%1, %2};" : "=l"(r) : "f"(x), "f"(y)); return r;
}
__device__ __forceinline__ ull dup2(float x) { return pack2(x, x); }
__device__ __forceinline__ float2 unpack2(ull v) {
    float2 r; asm("mov.b64 {%0, %1}, %2;" : "=f"(r.x), "=f"(r.y) : "l"(v)); return r;
}
__device__ __forceinline__ ull ldsu64(const float* p) {
    return *reinterpret_cast<const ull*>(p);
}
__device__ __forceinline__ void sts2(float* p, float x, float y) {
    *reinterpret_cast<float2*>(p) = make_float2(x, y);
}

__global__ void k_init(const float* __restrict__ emb_elec) {
    const int total = NB * NE * ED;
    for (int idx = blockIdx.x * blockDim.x + threadIdx.x; idx < total;
         idx += gridDim.x * blockDim.x) {
        int d = idx % ED, i = (idx / ED) % NE;
        g_xs[idx] = emb_elec[i * ED + d];
    }
}

// ---------------------------------------------------------------------------
// k_msg dynamic smem layout (floats):
//   zs2   [0, 2560)       f2[(jp)*64 + c] = (zs[2jp][c], zs[2jp+1][c]), jp=0..19
//   phase1 overlay: eiw_v [2560,10752) f2[q*32+c]=(W[q][c],W[q][c+32])
//                   xs2   [10752,14592) f2[p*128+q]=(xs[2p][q],xs[2p+1][q])
//   phase2 overlay: w1v [2560,4608) f2[q*32+c]; w2v [4608,7680) f2[k*32+c]
//                   db  [7680,9728)  per-warp 256 f (f2[g*32+q])
//                   h   [9728,12800) per-warp 384 f (f2[g*48+k])
// ---------------------------------------------------------------------------
#define MS_TOTAL_F 14592
#define MS_BYTES   (MS_TOTAL_F * 4)

__global__ void __launch_bounds__(256) k_msg(const float* __restrict__ dists,
                                             const float* __restrict__ emb_nuc,
                                             const float* __restrict__ eiw,
                                             const float* __restrict__ kw1,
                                             const float* __restrict__ kb1,
                                             const float* __restrict__ kw2,
                                             const float* __restrict__ kb2, int l) {
    extern __shared__ float sm[];
    float* zs2f  = sm;                 // 2560
    float* eiwv  = sm + 2560;          // 8192 (phase 1)
    float* xs2   = sm + 10752;         // 3840 (phase 1)
    float* w1v   = sm + 2560;          // 2048 (phase 2)
    float* w2v   = sm + 4608;          // 3072 (phase 2)
    float* dbr   = sm + 7680;          // 2048 (phase 2, per warp 256)
    float* hr    = sm + 9728;          // 3072 (phase 2, per warp 384)

    const int b = blockIdx.x, tid = threadIdx.x;
    const int w = tid >> 5, lane = tid & 31;

    // ---- phase 1a: stage eiw (interleaved), xs (i-pair interleaved), nuc zs ----
    {
        const float* W = eiw + (size_t)l * ED * KD;
        for (int t = tid; t < ED * 32; t += 256) {
            int q = t >> 5, c = t & 31;
            sts2(eiwv + 2 * t, W[q * KD + c], W[q * KD + c + 32]);
        }
        const float* xsb = g_xs + (size_t)b * NE * ED;
        for (int t = tid; t < 15 * ED; t += 256) {
            int p = t >> 7, q = t & 127;
            sts2(xs2 + 2 * t, xsb[(2 * p) * ED + q], xsb[(2 * p + 1) * ED + q]);
        }
        for (int idx = tid; idx < NN * KD; idx += 256) {
            int n = idx >> 6, c = idx & 63;
            int jp = (NE + n) >> 1, comp = n & 1;
            zs2f[(jp * 64 + c) * 2 + comp] = emb_nuc[n * KD + c];
        }
        if (tid < 128) zs2f[19 * 128 + tid] = 0.f;   // j = 38,39 pad
    }
    __syncthreads();

    // ---- phase 1b: electron zs (i-pairs packed in f32x2) ----
    for (int p = w; p < 15; p += 8) {
        ull acc0 = 0ull, acc1 = 0ull;
        const float* xrow = xs2 + p * 256;
        #pragma unroll 8
        for (int q = 0; q < ED; ++q) {
            ull x2 = ldsu64(xrow + 2 * q);                 // broadcast
            ull wv = ldsu64(eiwv + (q * 32 + lane) * 2);   // (w[q][lane], w[q][lane+32])
            float2 wf = unpack2(wv);
            acc0 = ffma2(x2, dup2(wf.x), acc0);
            acc1 = ffma2(x2, dup2(wf.y), acc1);
        }
        float2 a0 = unpack2(acc0), a1 = unpack2(acc1);
        sts2(zs2f + (p * 64 + lane) * 2, a0.x, a0.y);
        sts2(zs2f + (p * 64 + lane + 32) * 2, a1.x, a1.y);
    }
    __syncthreads();

    // ---- phase 2a: pair-MLP weights ----
    {
        const float* w1 = kw1 + (size_t)l * BASIS * HK;
        const float* w2 = kw2 + (size_t)l * HK * KD;
        for (int t = tid; t < BASIS * 32; t += 256) {
            int q = t >> 5, c = t & 31;
            float x = w1[q * HK + c];
            float y = (c + 32 < HK) ? w1[q * HK + c + 32] : 0.f;
            sts2(w1v + 2 * t, x, y);
        }
        for (int t = tid; t < HKP * 32; t += 256) {
            int k = t >> 5, c = t & 31;
            float x = (k < HK) ? w2[k * KD + c] : 0.f;
            float y = (k < HK) ? w2[k * KD + c + 32] : 0.f;
            sts2(w2v + 2 * t, x, y);
        }
    }
    __syncthreads();

    const float* b1 = kb1 + (size_t)l * HK;
    const float* b2 = kb2 + (size_t)l * KD;
    const ull db1x = dup2(b1[lane]);
    const ull db1y = dup2((lane + 32 < HK) ? b1[lane + 32] : 0.f);
    const ull db2x = dup2(b2[lane]);
    const ull db2y = dup2(b2[lane + 32]);

    float* dbw = dbr + w * 256;   // f2[g*32+q]
    float* hw  = hr  + w * 384;   // f2[g*48+k]

    for (int i = w; i < NE; i += 8) {
        const float* dbase = dists + ((size_t)(b * NE + i)) * NA * BASIS;
        ull mx = 0ull, my = 0ull;

        for (int jg = 0; jg < 5; ++jg) {
            const int j0 = jg * 8;
            // ---- stage 8 db rows as 4 pair-interleaved f2 columns ----
            float v0 = dbase[(j0 + 0) * BASIS + lane];
            float v1 = dbase[(j0 + 1) * BASIS + lane];
            float v2 = dbase[(j0 + 2) * BASIS + lane];
            float v3 = dbase[(j0 + 3) * BASIS + lane];
            float v4 = dbase[(j0 + 4) * BASIS + lane];
            float v5 = dbase[(j0 + 5) * BASIS + lane];
            float v6 = (j0 + 6 < NA) ? dbase[(j0 + 6) * BASIS + lane] : 0.f;
            float v7 = (j0 + 7 < NA) ? dbase[(j0 + 7) * BASIS + lane] : 0.f;
            sts2(dbw + (0 * 32 + lane) * 2, v0, v1);
            sts2(dbw + (1 * 32 + lane) * 2, v2, v3);
            sts2(dbw + (2 * 32 + lane) * 2, v4, v5);
            sts2(dbw + (3 * 32 + lane) * 2, v6, v7);
            __syncwarp();

            // ---- GEMM1: a = db @ w1 + b1 ----
            ull a0x = db1x, a1x = db1x, a2x = db1x, a3x = db1x;
            ull a0y = db1y, a1y = db1y, a2y = db1y, a3y = db1y;
            #pragma unroll
            for (int q = 0; q < BASIS; ++q) {
                ull d0 = ldsu64(dbw + (0 * 32 + q) * 2);
                ull d1 = ldsu64(dbw + (1 * 32 + q) * 2);
                ull d2 = ldsu64(dbw + (2 * 32 + q) * 2);
                ull d3 = ldsu64(dbw + (3 * 32 + q) * 2);
                float2 wf = unpack2(ldsu64(w1v + (q * 32 + lane) * 2));
                ull wxx = dup2(wf.x), wyy = dup2(wf.y);
                a0x = ffma2(d0, wxx, a0x); a0y = ffma2(d0, wyy, a0y);
                a1x = ffma2(d1, wxx, a1x); a1y = ffma2(d1, wyy, a1y);
                a2x = ffma2(d2, wxx, a2x); a2y = ffma2(d2, wyy, a2y);
                a3x = ffma2(d3, wxx, a3x); a3y = ffma2(d3, wyy, a3y);
            }
            // ---- ssp -> h ----
            {
                float2 t;
                t = unpack2(a0x); sts2(hw + (0 * 48 + lane) * 2, ssp(t.x), ssp(t.y));
                t = unpack2(a1x); sts2(hw + (1 * 48 + lane) * 2, ssp(t.x), ssp(t.y));
                t = unpack2(a2x); sts2(hw + (2 * 48 + lane) * 2, ssp(t.x), ssp(t.y));
                t = unpack2(a3x); sts2(hw + (3 * 48 + lane) * 2, ssp(t.x), ssp(t.y));
                if (lane < 16) {
                    t = unpack2(a0y); sts2(hw + (0 * 48 + lane + 32) * 2, ssp(t.x), ssp(t.y));
                    t = unpack2(a1y); sts2(hw + (1 * 48 + lane + 32) * 2, ssp(t.x), ssp(t.y));
                    t = unpack2(a2y); sts2(hw + (2 * 48 + lane + 32) * 2, ssp(t.x), ssp(t.y));
                    t = unpack2(a3y); sts2(hw + (3 * 48 + lane + 32) * 2, ssp(t.x), ssp(t.y));
                }
            }
            __syncwarp();

            // ---- GEMM2: Ws = h @ w2 + b2 ----
            ull c0x = db2x, c1x = db2x, c2x = db2x, c3x = db2x;
            ull c0y = db2y, c1y = db2y, c2y = db2y, c3y = db2y;
            #pragma unroll
            for (int k = 0; k < HKP; ++k) {
                ull h0 = ldsu64(hw + (0 * 48 + k) * 2);
                ull h1 = ldsu64(hw + (1 * 48 + k) * 2);
                ull h2 = ldsu64(hw + (2 * 48 + k) * 2);
                ull h3 = ldsu64(hw + (3 * 48 + k) * 2);
                float2 wf = unpack2(ldsu64(w2v + (k * 32 + lane) * 2));
                ull wxx = dup2(wf.x), wyy = dup2(wf.y);
                c0x = ffma2(h0, wxx, c0x); c0y = ffma2(h0, wyy, c0y);
                c1x = ffma2(h1, wxx, c1x); c1y = ffma2(h1, wyy, c1y);
                c2x = ffma2(h2, wxx, c2x); c2y = ffma2(h2, wyy, c2y);
                c3x = ffma2(h3, wxx, c3x); c3y = ffma2(h3, wyy, c3y);
            }

            // ---- msg += Ws * zs[j] (mask j == i; j >= NA handled by zero pads) ----
            #pragma unroll
            for (int g = 0; g < 4; ++g) {
                int jp = jg * 4 + g;
                int je = j0 + 2 * g;
                float2 zx = *reinterpret_cast<float2*>(zs2f + (jp * 64 + lane) * 2);
                float2 zy = *reinterpret_cast<float2*>(zs2f + (jp * 64 + lane + 32) * 2);
                if (je == i)     { zx.x = 0.f; zy.x = 0.f; }
                if (je + 1 == i) { zx.y = 0.f; zy.y = 0.f; }
                ull cx = (g == 0) ? c0x : (g == 1) ? c1x : (g == 2) ? c2x : c3x;
                ull cy = (g == 0) ? c0y : (g == 1) ? c1y : (g == 2) ? c2y : c3y;
                mx = ffma2(cx, pack2(zx.x, zx.y), mx);
                my = ffma2(cy, pack2(zy.x, zy.y), my);
            }
            __syncwarp();
        }
        float2 u = unpack2(mx), v = unpack2(my);
        float* mp = g_msg + ((size_t)(b * NE + i)) * KD;
        mp[lane]      = u.x + u.y;
        mp[lane + 32] = v.x + v.y;
    }
}

// ---------------------------------------------------------------------------
// k_out dynamic smem (floats):
//   smsg2 [0,1920)      f2[p*64+q] = (msg[2p][q], msg[2p+1][q])
//   sw1d  [1920,8064)   f2[q*48+c] = (W1[q][c], W1[q][c+48]), pad cols>=91 -> 0
//   sw2d  [8064,20352)  f2[k*64+c] = (W2[k][c], W2[k][c+64]), pad rows>=91 -> 0
//   sb1   [20352,20480) 128 floats (pad zeros past 91)
//   sb2   [20480,20608) 128 floats
//   sh2   [20608,22144) per-warp f2[96] = (h_i0[k], h_i1[k])
// ---------------------------------------------------------------------------
#define VO_TOTAL_F 22144
#define VO_BYTES   (VO_TOTAL_F * 4)

__global__ void __launch_bounds__(256) k_out(const float* __restrict__ ow1,
                                             const float* __restrict__ ob1,
                                             const float* __restrict__ ow2,
                                             const float* __restrict__ ob2,
                                             int l, float* __restrict__ xs_out) {
    extern __shared__ float smo[];
    float* smsg2 = smo;
    float* sw1d  = smo + 1920;
    float* sw2d  = smo + 8064;
    float* sb1   = smo + 20352;
    float* sb2   = smo + 20480;
    float* sh2a  = smo + 20608;

    const int b = blockIdx.x, tid = threadIdx.x;
    const int w = tid >> 5, lane = tid & 31;
    const float* W1 = ow1 + (size_t)l * KD * HO;
    const float* B1 = ob1 + (size_t)l * HO;
    const float* W2 = ow2 + (size_t)l * HO * ED;
    const float* B2 = ob2 + (size_t)l * ED;

    {
        const float* mg = g_msg + (size_t)b * NE * KD;
        for (int t = tid; t < 15 * KD; t += 256) {
            int p = t >> 6, q = t & 63;
            sts2(smsg2 + 2 * t, mg[(2 * p) * KD + q], mg[(2 * p + 1) * KD + q]);
        }
        for (int t = tid; t < KD * 48; t += 256) {
            int q = t / 48, c = t % 48;
            float x = (c < HO) ? W1[q * HO + c] : 0.f;
            float y = (c + 48 < HO) ? W1[q * HO + c + 48] : 0.f;
            sts2(sw1d + 2 * t, x, y);
        }
        for (int t = tid; t < HOP * 64; t += 256) {
            int k = t >> 6, c = t & 63;
            float x = (k < HO) ? W2[k * ED + c] : 0.f;
            float y = (k < HO) ? W2[k * ED + c + 64] : 0.f;
            sts2(sw2d + 2 * t, x, y);
        }
        for (int t = tid; t < 128; t += 256) {
            sb1[t] = (t < HO) ? B1[t] : 0.f;
            sb2[t] = B2[t];
        }
    }
    __syncthreads();

    const ull bA0x = dup2(sb1[lane]);
    const ull bA0y = dup2(sb1[lane + 48]);
    const ull bA1x = dup2(sb1[lane + 32]);
    const ull bA1y = dup2(sb1[lane + 80]);
    const ull bC0 = dup2(sb2[lane]);
    const ull bC1 = dup2(sb2[lane + 32]);
    const ull bC2 = dup2(sb2[lane + 64]);
    const ull bC3 = dup2(sb2[lane + 96]);

    float* sh2 = sh2a + w * 192;  // f2[96]

    for (int p = w; p < 15; p += 8) {
        // ---- GEMM1: a = msg @ W1 + b1, i-pair packed ----
        ull A0x = bA0x, A0y = bA0y, A1x = bA1x, A1y = bA1y;
        const float* mrow = smsg2 + p * 128;
        #pragma unroll
        for (int q = 0; q < KD; ++q) {
            ull m2 = ldsu64(mrow + 2 * q);                         // broadcast
            float2 w0 = unpack2(ldsu64(sw1d + (q * 48 + lane) * 2));
            float2 w1f = unpack2(ldsu64(sw1d + (q * 48 + lane + 32) * 2)); // junk lanes>=16, discarded
            A0x = ffma2(m2, dup2(w0.x), A0x);
            A0y = ffma2(m2, dup2(w0.y), A0y);
            A1x = ffma2(m2, dup2(w1f.x), A1x);
            A1y = ffma2(m2, dup2(w1f.y), A1y);
        }
        {
            float2 t;
            t = unpack2(A0x); sts2(sh2 + (lane) * 2,      ssp(t.x), ssp(t.y));
            t = unpack2(A0y); sts2(sh2 + (lane + 48) * 2, ssp(t.x), ssp(t.y));
            if (lane < 16) {
                t = unpack2(A1x); sts2(sh2 + (lane + 32) * 2, ssp(t.x), ssp(t.y));
                t = unpack2(A1y); sts2(sh2 + (lane + 80) * 2, ssp(t.x), ssp(t.y));
            }
        }
        __syncwarp();

        // ---- GEMM2: v = h @ W2 + b2, i-pair packed ----
        ull C0 = bC0, C1 = bC1, C2 = bC2, C3 = bC3;
        #pragma unroll
        for (int k = 0; k < HOP; ++k) {
            ull h2 = ldsu64(sh2 + 2 * k);                          // broadcast
            float2 w0 = unpack2(ldsu64(sw2d + (k * 64 + lane) * 2));
            float2 w1f = unpack2(ldsu64(sw2d + (k * 64 + lane + 32) * 2));
            C0 = ffma2(h2, dup2(w0.x), C0);
            C2 = ffma2(h2, dup2(w0.y), C2);
            C1 = ffma2(h2, dup2(w1f.x), C1);
            C3 = ffma2(h2, dup2(w1f.y), C3);
        }
        __syncwarp();

        // ---- residual + store both electrons ----
        int i0 = 2 * p, i1 = 2 * p + 1;
        size_t b0 = ((size_t)(b * NE + i0)) * ED;
        size_t b1o = ((size_t)(b * NE + i1)) * ED;
        float2 c0 = unpack2(C0), c1 = unpack2(C1), c2 = unpack2(C2), c3 = unpack2(C3);
        xs_out[b0 + lane]       = g_xs[b0 + lane]       + c0.x;
        xs_out[b0 + lane + 32]  = g_xs[b0 + lane + 32]  + c1.x;
        xs_out[b0 + lane + 64]  = g_xs[b0 + lane + 64]  + c2.x;
        xs_out[b0 + lane + 96]  = g_xs[b0 + lane + 96]  + c3.x;
        xs_out[b1o + lane]      = g_xs[b1o + lane]      + c0.y;
        xs_out[b1o + lane + 32] = g_xs[b1o + lane + 32] + c1.y;
        xs_out[b1o + lane + 64] = g_xs[b1o + lane + 64] + c2.y;
        xs_out[b1o + lane + 96] = g_xs[b1o + lane + 96] + c3.y;
    }
}

// ---------------------------------------------------------------------------
extern "C" void kernel_launch(void* const* d_in, const int* in_sizes, int n_in,
                              void* d_out, int out_size) {
    const float* dists    = (const float*)d_in[0];
    const float* emb_elec = (const float*)d_in[1];
    const float* emb_nuc  = (const float*)d_in[2];
    const float* kw1      = (const float*)d_in[3];
    const float* kb1      = (const float*)d_in[4];
    const float* kw2      = (const float*)d_in[5];
    const float* kb2      = (const float*)d_in[6];
    const float* eiw      = (const float*)d_in[7];
    const float* ow1      = (const float*)d_in[8];
    const float* ob1      = (const float*)d_in[9];
    const float* ow2      = (const float*)d_in[10];
    const float* ob2      = (const float*)d_in[11];
    float* out = (float*)d_out;

    static int configured = 0;
    if (!configured) {
        cudaFuncSetAttribute(k_msg, cudaFuncAttributeMaxDynamicSharedMemorySize, MS_BYTES);
        cudaFuncSetAttribute(k_out, cudaFuncAttributeMaxDynamicSharedMemorySize, VO_BYTES);
        configured = 1;
    }
    void* xsptr = nullptr;
    cudaGetSymbolAddress(&xsptr, g_xs);

    k_init<<<4096, 256>>>(emb_elec);
    for (int l = 0; l < NL; ++l) {
        k_msg<<<NB, 256, MS_BYTES>>>(dists, emb_nuc, eiw, kw1, kb1, kw2, kb2, l);
        float* xs_out = (l == NL - 1) ? out : (float*)xsptr;
        k_out<<<NB, 256, VO_BYTES>>>(ow1, ob1, ow2, ob2, l, xs_out);
    }
}

// round 5
// speedup vs baseline: 2.3903x; 1.0096x over previous
#include <cuda_runtime.h>

#define NB    2048
#define NE    30
#define NA    38
#define NN    8
#define BASIS 32
#define KD    64
#define ED    128
#define HK    45
#define HKP   48
#define HO    91
#define HOP   96
#define NL    3

typedef unsigned long long ull;

__device__ float g_xs [NB * NE * ED];
__device__ float g_msg[NB * NE * KD];

__device__ __forceinline__ float ssp(float x) {
    float t = __expf(-fabsf(x));
    return fmaxf(x, 0.f) + __logf(1.f + t) - 0.69314718055994530942f;
}
__device__ __forceinline__ ull ffma2(ull a, ull b, ull c) {
    ull d; asm("fma.rn.f32x2 %0, %1, %2, %3;" : "=l"(d) : "l"(a), "l"(b), "l"(c));
    return d;
}
__device__ __forceinline__ ull pack2(float x, float y) {
    ull r; asm("mov.b64 %0, {%1, %2};" : "=l"(r) : "f"(x), "f"(y)); return r;
}
__device__ __forceinline__ ull dup2(float x) { return pack2(x, x); }
__device__ __forceinline__ float2 unpack2(ull v) {
    float2 r; asm("mov.b64 {%0, %1}, %2;" : "=f"(r.x), "=f"(r.y) : "l"(v)); return r;
}
__device__ __forceinline__ ull ldsu64(const float* p) {
    return *reinterpret_cast<const ull*>(p);
}
__device__ __forceinline__ void sts2(float* p, float x, float y) {
    *reinterpret_cast<float2*>(p) = make_float2(x, y);
}

__global__ void k_init(const float* __restrict__ emb_elec) {
    const int total = NB * NE * ED;
    for (int idx = blockIdx.x * blockDim.x + threadIdx.x; idx < total;
         idx += gridDim.x * blockDim.x) {
        int d = idx % ED, i = (idx / ED) % NE;
        g_xs[idx] = emb_elec[i * ED + d];
    }
}

// ---------------------------------------------------------------------------
// k_msg smem layout (floats):
//   zs2f [0,2560)       f2[jp*64+c] = (zs[2jp][c], zs[2jp+1][c]), jp 0..19
//   w1v  [2560,4608)    f2[q*32+c]  = (w1[q][c], w1[q][c+32] or 0)
//   w2v  [4608,7680)    f2[k*32+c]  = (w2[k][c], w2[k][c+32]), rows>=45 zero
//   db4  [7680,12800)   per warp 640 f: f4[q*5+g] = db rows (4g..4g+3) at q
//   h4   [12800,20480)  per warp 960 f: f4[k*5+g] = h rows (4g..4g+3) at k
//   phase1 overlay: eiwv [2560,10752), xs2 [12800,16640)
// ---------------------------------------------------------------------------
#define MS_TOTAL_F 20480
#define MS_BYTES   (MS_TOTAL_F * 4)

__global__ void __launch_bounds__(256) k_msg(const float* __restrict__ dists,
                                             const float* __restrict__ emb_nuc,
                                             const float* __restrict__ eiw,
                                             const float* __restrict__ kw1,
                                             const float* __restrict__ kb1,
                                             const float* __restrict__ kw2,
                                             const float* __restrict__ kb2, int l) {
    extern __shared__ float sm[];
    float* zs2f = sm;                  // 2560
    float* w1v  = sm + 2560;           // 2048
    float* w2v  = sm + 4608;           // 3072
    float* db4  = sm + 7680;           // 5120 (per warp 640)
    float* h4   = sm + 12800;          // 7680 (per warp 960)
    float* eiwv = sm + 2560;           // phase-1 overlay
    float* xs2  = sm + 12800;          // phase-1 overlay

    const int b = blockIdx.x, tid = threadIdx.x;
    const int w = tid >> 5, lane = tid & 31;

    // ---- phase 1a: stage eiw + xs + nuclear zs ----
    {
        const float* W = eiw + (size_t)l * ED * KD;
        for (int t = tid; t < ED * 32; t += 256) {
            int q = t >> 5, c = t & 31;
            sts2(eiwv + 2 * t, W[q * KD + c], W[q * KD + c + 32]);
        }
        const float* xsb = g_xs + (size_t)b * NE * ED;
        for (int t = tid; t < 15 * ED; t += 256) {
            int p = t >> 7, q = t & 127;
            sts2(xs2 + 2 * t, xsb[(2 * p) * ED + q], xsb[(2 * p + 1) * ED + q]);
        }
        for (int idx = tid; idx < NN * KD; idx += 256) {
            int n = idx >> 6, c = idx & 63;
            int jp = (NE + n) >> 1, comp = n & 1;
            zs2f[(jp * 64 + c) * 2 + comp] = emb_nuc[n * KD + c];
        }
        if (tid < 128) zs2f[19 * 128 + tid] = 0.f;   // j = 38,39 pad
    }
    __syncthreads();

    // ---- phase 1b: electron zs (i-pairs packed f32x2) ----
    for (int p = w; p < 15; p += 8) {
        ull acc0 = 0ull, acc1 = 0ull;
        const float* xrow = xs2 + p * 256;
        #pragma unroll 8
        for (int q = 0; q < ED; ++q) {
            ull x2 = ldsu64(xrow + 2 * q);
            float2 wf = unpack2(ldsu64(eiwv + (q * 32 + lane) * 2));
            acc0 = ffma2(x2, dup2(wf.x), acc0);
            acc1 = ffma2(x2, dup2(wf.y), acc1);
        }
        float2 a0 = unpack2(acc0), a1 = unpack2(acc1);
        sts2(zs2f + (p * 64 + lane) * 2, a0.x, a0.y);
        sts2(zs2f + (p * 64 + lane + 32) * 2, a1.x, a1.y);
    }
    __syncthreads();

    // ---- phase 2a: pair-MLP weights ----
    {
        const float* w1 = kw1 + (size_t)l * BASIS * HK;
        const float* w2 = kw2 + (size_t)l * HK * KD;
        for (int t = tid; t < BASIS * 32; t += 256) {
            int q = t >> 5, c = t & 31;
            float x = w1[q * HK + c];
            float y = (c + 32 < HK) ? w1[q * HK + c + 32] : 0.f;
            sts2(w1v + 2 * t, x, y);
        }
        for (int t = tid; t < HKP * 32; t += 256) {
            int k = t >> 5, c = t & 31;
            float x = (k < HK) ? w2[k * KD + c] : 0.f;
            float y = (k < HK) ? w2[k * KD + c + 32] : 0.f;
            sts2(w2v + 2 * t, x, y);
        }
    }
    __syncthreads();

    const float* b1 = kb1 + (size_t)l * HK;
    const float* b2 = kb2 + (size_t)l * KD;
    const ull db1x = dup2(b1[lane]);
    const ull db1y = dup2((lane + 32 < HK) ? b1[lane + 32] : 0.f);
    const ull db2x = dup2(b2[lane]);
    const ull db2y = dup2(b2[lane + 32]);

    float* dbw = db4 + w * 640;
    float* hw  = h4  + w * 960;

    for (int i = w; i < NE; i += 8) {
        const float* dbase = dists + ((size_t)(b * NE + i)) * NA * BASIS;
        ull mx = 0ull, my = 0ull;

        for (int half = 0; half < 2; ++half) {
            const int j0 = half * 20;

            // ---- stage 20 db rows as float4 groups of 4 rows ----
            float v[20];
            #pragma unroll
            for (int r = 0; r < 20; ++r) {
                int j = j0 + r;
                v[r] = (j < NA) ? dbase[j * BASIS + lane] : 0.f;
            }
            #pragma unroll
            for (int g = 0; g < 5; ++g)
                *reinterpret_cast<float4*>(dbw + (lane * 5 + g) * 4) =
                    make_float4(v[4*g], v[4*g+1], v[4*g+2], v[4*g+3]);
            __syncwarp();

            // ---- GEMM1: a = db @ w1 + b1 ----
            ull a01x[5], a23x[5], a01y[5], a23y[5];
            #pragma unroll
            for (int g = 0; g < 5; ++g) {
                a01x[g] = db1x; a23x[g] = db1x;
                a01y[g] = db1y; a23y[g] = db1y;
            }
            #pragma unroll 8
            for (int q = 0; q < BASIS; ++q) {
                float2 wf = unpack2(ldsu64(w1v + (q * 32 + lane) * 2));
                ull wxx = dup2(wf.x), wyy = dup2(wf.y);
                #pragma unroll
                for (int g = 0; g < 5; ++g) {
                    ulonglong2 d = *reinterpret_cast<const ulonglong2*>(dbw + (q * 5 + g) * 4);
                    a01x[g] = ffma2(d.x, wxx, a01x[g]);
                    a23x[g] = ffma2(d.y, wxx, a23x[g]);
                    a01y[g] = ffma2(d.x, wyy, a01y[g]);
                    a23y[g] = ffma2(d.y, wyy, a23y[g]);
                }
            }
            __syncwarp();

            // ---- ssp -> h (float4 row-group layout) ----
            #pragma unroll
            for (int g = 0; g < 5; ++g) {
                float2 t = unpack2(a01x[g]);
                float2 u = unpack2(a23x[g]);
                sts2(hw + (lane * 5 + g) * 4,     ssp(t.x), ssp(t.y));
                sts2(hw + (lane * 5 + g) * 4 + 2, ssp(u.x), ssp(u.y));
                if (lane < 16) {
                    float2 ty = unpack2(a01y[g]);
                    float2 uy = unpack2(a23y[g]);
                    sts2(hw + ((lane + 32) * 5 + g) * 4,     ssp(ty.x), ssp(ty.y));
                    sts2(hw + ((lane + 32) * 5 + g) * 4 + 2, ssp(uy.x), ssp(uy.y));
                }
            }
            __syncwarp();

            // ---- GEMM2: Ws = h @ w2 + b2 (k < 45; pad rows skipped) ----
            ull c01x[5], c23x[5], c01y[5], c23y[5];
            #pragma unroll
            for (int g = 0; g < 5; ++g) {
                c01x[g] = db2x; c23x[g] = db2x;
                c01y[g] = db2y; c23y[g] = db2y;
            }
            #pragma unroll 5
            for (int k = 0; k < HK; ++k) {
                float2 wf = unpack2(ldsu64(w2v + (k * 32 + lane) * 2));
                ull wxx = dup2(wf.x), wyy = dup2(wf.y);
                #pragma unroll
                for (int g = 0; g < 5; ++g) {
                    ulonglong2 h2 = *reinterpret_cast<const ulonglong2*>(hw + (k * 5 + g) * 4);
                    c01x[g] = ffma2(h2.x, wxx, c01x[g]);
                    c23x[g] = ffma2(h2.y, wxx, c23x[g]);
                    c01y[g] = ffma2(h2.x, wyy, c01y[g]);
                    c23y[g] = ffma2(h2.y, wyy, c23y[g]);
                }
            }

            // ---- msg += Ws * zs[j] (mask j == i; pads are zero in zs) ----
            #pragma unroll
            for (int g = 0; g < 5; ++g) {
                int jb  = j0 + 4 * g;
                int jp0 = half * 10 + 2 * g;
                float2 z0x = *reinterpret_cast<float2*>(zs2f + (jp0 * 64 + lane) * 2);
                float2 z0y = *reinterpret_cast<float2*>(zs2f + (jp0 * 64 + lane + 32) * 2);
                float2 z1x = *reinterpret_cast<float2*>(zs2f + ((jp0 + 1) * 64 + lane) * 2);
                float2 z1y = *reinterpret_cast<float2*>(zs2f + ((jp0 + 1) * 64 + lane + 32) * 2);
                if (jb     == i) { z0x.x = 0.f; z0y.x = 0.f; }
                if (jb + 1 == i) { z0x.y = 0.f; z0y.y = 0.f; }
                if (jb + 2 == i) { z1x.x = 0.f; z1y.x = 0.f; }
                if (jb + 3 == i) { z1x.y = 0.f; z1y.y = 0.f; }
                mx = ffma2(c01x[g], pack2(z0x.x, z0x.y), mx);
                my = ffma2(c01y[g], pack2(z0y.x, z0y.y), my);
                mx = ffma2(c23x[g], pack2(z1x.x, z1x.y), mx);
                my = ffma2(c23y[g], pack2(z1y.x, z1y.y), my);
            }
            __syncwarp();
        }
        float2 u = unpack2(mx), vv = unpack2(my);
        float* mp = g_msg + ((size_t)(b * NE + i)) * KD;
        mp[lane]      = u.x + u.y;
        mp[lane + 32] = vv.x + vv.y;
    }
}

// ---------------------------------------------------------------------------
// k_out (unchanged from R3/R4 passing version)
// ---------------------------------------------------------------------------
#define VO_TOTAL_F 22144
#define VO_BYTES   (VO_TOTAL_F * 4)

__global__ void __launch_bounds__(256) k_out(const float* __restrict__ ow1,
                                             const float* __restrict__ ob1,
                                             const float* __restrict__ ow2,
                                             const float* __restrict__ ob2,
                                             int l, float* __restrict__ xs_out) {
    extern __shared__ float smo[];
    float* smsg2 = smo;
    float* sw1d  = smo + 1920;
    float* sw2d  = smo + 8064;
    float* sb1   = smo + 20352;
    float* sb2   = smo + 20480;
    float* sh2a  = smo + 20608;

    const int b = blockIdx.x, tid = threadIdx.x;
    const int w = tid >> 5, lane = tid & 31;
    const float* W1 = ow1 + (size_t)l * KD * HO;
    const float* B1 = ob1 + (size_t)l * HO;
    const float* W2 = ow2 + (size_t)l * HO * ED;
    const float* B2 = ob2 + (size_t)l * ED;

    {
        const float* mg = g_msg + (size_t)b * NE * KD;
        for (int t = tid; t < 15 * KD; t += 256) {
            int p = t >> 6, q = t & 63;
            sts2(smsg2 + 2 * t, mg[(2 * p) * KD + q], mg[(2 * p + 1) * KD + q]);
        }
        for (int t = tid; t < KD * 48; t += 256) {
            int q = t / 48, c = t % 48;
            float x = (c < HO) ? W1[q * HO + c] : 0.f;
            float y = (c + 48 < HO) ? W1[q * HO + c + 48] : 0.f;
            sts2(sw1d + 2 * t, x, y);
        }
        for (int t = tid; t < HOP * 64; t += 256) {
            int k = t >> 6, c = t & 63;
            float x = (k < HO) ? W2[k * ED + c] : 0.f;
            float y = (k < HO) ? W2[k * ED + c + 64] : 0.f;
            sts2(sw2d + 2 * t, x, y);
        }
        for (int t = tid; t < 128; t += 256) {
            sb1[t] = (t < HO) ? B1[t] : 0.f;
            sb2[t] = B2[t];
        }
    }
    __syncthreads();

    const ull bA0x = dup2(sb1[lane]);
    const ull bA0y = dup2(sb1[lane + 48]);
    const ull bA1x = dup2(sb1[lane + 32]);
    const ull bA1y = dup2(sb1[lane + 80]);
    const ull bC0 = dup2(sb2[lane]);
    const ull bC1 = dup2(sb2[lane + 32]);
    const ull bC2 = dup2(sb2[lane + 64]);
    const ull bC3 = dup2(sb2[lane + 96]);

    float* sh2 = sh2a + w * 192;

    for (int p = w; p < 15; p += 8) {
        ull A0x = bA0x, A0y = bA0y, A1x = bA1x, A1y = bA1y;
        const float* mrow = smsg2 + p * 128;
        #pragma unroll
        for (int q = 0; q < KD; ++q) {
            ull m2 = ldsu64(mrow + 2 * q);
            float2 w0 = unpack2(ldsu64(sw1d + (q * 48 + lane) * 2));
            float2 w1f = unpack2(ldsu64(sw1d + (q * 48 + lane + 32) * 2));
            A0x = ffma2(m2, dup2(w0.x), A0x);
            A0y = ffma2(m2, dup2(w0.y), A0y);
            A1x = ffma2(m2, dup2(w1f.x), A1x);
            A1y = ffma2(m2, dup2(w1f.y), A1y);
        }
        {
            float2 t;
            t = unpack2(A0x); sts2(sh2 + (lane) * 2,      ssp(t.x), ssp(t.y));
            t = unpack2(A0y); sts2(sh2 + (lane + 48) * 2, ssp(t.x), ssp(t.y));
            if (lane < 16) {
                t = unpack2(A1x); sts2(sh2 + (lane + 32) * 2, ssp(t.x), ssp(t.y));
                t = unpack2(A1y); sts2(sh2 + (lane + 80) * 2, ssp(t.x), ssp(t.y));
            }
        }
        __syncwarp();

        ull C0 = bC0, C1 = bC1, C2 = bC2, C3 = bC3;
        #pragma unroll
        for (int k = 0; k < HOP; ++k) {
            ull h2 = ldsu64(sh2 + 2 * k);
            float2 w0 = unpack2(ldsu64(sw2d + (k * 64 + lane) * 2));
            float2 w1f = unpack2(ldsu64(sw2d + (k * 64 + lane + 32) * 2));
            C0 = ffma2(h2, dup2(w0.x), C0);
            C2 = ffma2(h2, dup2(w0.y), C2);
            C1 = ffma2(h2, dup2(w1f.x), C1);
            C3 = ffma2(h2, dup2(w1f.y), C3);
        }
        __syncwarp();

        int i0 = 2 * p, i1 = 2 * p + 1;
        size_t b0 = ((size_t)(b * NE + i0)) * ED;
        size_t b1o = ((size_t)(b * NE + i1)) * ED;
        float2 c0 = unpack2(C0), c1 = unpack2(C1), c2 = unpack2(C2), c3 = unpack2(C3);
        xs_out[b0 + lane]       = g_xs[b0 + lane]       + c0.x;
        xs_out[b0 + lane + 32]  = g_xs[b0 + lane + 32]  + c1.x;
        xs_out[b0 + lane + 64]  = g_xs[b0 + lane + 64]  + c2.x;
        xs_out[b0 + lane + 96]  = g_xs[b0 + lane + 96]  + c3.x;
        xs_out[b1o + lane]      = g_xs[b1o + lane]      + c0.y;
        xs_out[b1o + lane + 32] = g_xs[b1o + lane + 32] + c1.y;
        xs_out[b1o + lane + 64] = g_xs[b1o + lane + 64] + c2.y;
        xs_out[b1o + lane + 96] = g_xs[b1o + lane + 96] + c3.y;
    }
}

// ---------------------------------------------------------------------------
extern "C" void kernel_launch(void* const* d_in, const int* in_sizes, int n_in,
                              void* d_out, int out_size) {
    const float* dists    = (const float*)d_in[0];
    const float* emb_elec = (const float*)d_in[1];
    const float* emb_nuc  = (const float*)d_in[2];
    const float* kw1      = (const float*)d_in[3];
    const float* kb1      = (const float*)d_in[4];
    const float* kw2      = (const float*)d_in[5];
    const float* kb2      = (const float*)d_in[6];
    const float* eiw      = (const float*)d_in[7];
    const float* ow1      = (const float*)d_in[8];
    const float* ob1      = (const float*)d_in[9];
    const float* ow2      = (const float*)d_in[10];
    const float* ob2      = (const float*)d_in[11];
    float* out = (float*)d_out;

    static int configured = 0;
    if (!configured) {
        cudaFuncSetAttribute(k_msg, cudaFuncAttributeMaxDynamicSharedMemorySize, MS_BYTES);
        cudaFuncSetAttribute(k_out, cudaFuncAttributeMaxDynamicSharedMemorySize, VO_BYTES);
        configured = 1;
    }
    void* xsptr = nullptr;
    cudaGetSymbolAddress(&xsptr, g_xs);

    k_init<<<4096, 256>>>(emb_elec);
    for (int l = 0; l < NL; ++l) {
        k_msg<<<NB, 256, MS_BYTES>>>(dists, emb_nuc, eiw, kw1, kb1, kw2, kb2, l);
        float* xs_out = (l == NL - 1) ? out : (float*)xsptr;
        k_out<<<NB, 256, VO_BYTES>>>(ow1, ob1, ow2, ob2, l, xs_out);
    }
}

// round 6
// speedup vs baseline: 3.1982x; 1.3380x over previous
#include <cuda_runtime.h>

#define NB    2048
#define NE    30
#define NA    38
#define NN    8
#define BASIS 32
#define KD    64
#define ED    128
#define HK    45
#define HO    91
#define HOP   96
#define NL    3

typedef unsigned long long ull;
typedef unsigned int uint32;

__device__ float g_xs [NB * NE * ED];
__device__ float g_msg[NB * NE * KD];

__device__ __forceinline__ float ssp(float x) {
    float t = __expf(-fabsf(x));
    return fmaxf(x, 0.f) + __logf(1.f + t) - 0.69314718055994530942f;
}
__device__ __forceinline__ ull ffma2(ull a, ull b, ull c) {
    ull d; asm("fma.rn.f32x2 %0, %1, %2, %3;" : "=l"(d) : "l"(a), "l"(b), "l"(c));
    return d;
}
__device__ __forceinline__ ull pack2(float x, float y) {
    ull r; asm("mov.b64 %0, {%1, %2};" : "=l"(r) : "f"(x), "f"(y)); return r;
}
__device__ __forceinline__ ull dup2(float x) { return pack2(x, x); }
__device__ __forceinline__ float2 unpack2(ull v) {
    float2 r; asm("mov.b64 {%0, %1}, %2;" : "=f"(r.x), "=f"(r.y) : "l"(v)); return r;
}
__device__ __forceinline__ ull ldsu64(const float* p) {
    return *reinterpret_cast<const ull*>(p);
}
__device__ __forceinline__ void sts2(float* p, float x, float y) {
    *reinterpret_cast<float2*>(p) = make_float2(x, y);
}
__device__ __forceinline__ uint32 f2tf(float x) {
    uint32 u; asm("cvt.rna.tf32.f32 %0, %1;" : "=r"(u) : "f"(x)); return u;
}
// D += A(16x8) * B(8x8), tf32, fp32 accum. Standard m16n8k8 fragment layout.
__device__ __forceinline__ void mma8(float& d0, float& d1, float& d2, float& d3,
                                     uint32 a0, uint32 a1, uint32 a2, uint32 a3,
                                     uint32 b0, uint32 b1) {
    asm volatile(
        "mma.sync.aligned.m16n8k8.row.col.f32.tf32.tf32.f32 "
        "{%0,%1,%2,%3},{%4,%5,%6,%7},{%8,%9},{%0,%1,%2,%3};"
        : "+f"(d0), "+f"(d1), "+f"(d2), "+f"(d3)
        : "r"(a0), "r"(a1), "r"(a2), "r"(a3), "r"(b0), "r"(b1));
}

__global__ void k_init(const float* __restrict__ emb_elec) {
    const int total = NB * NE * ED;
    for (int idx = blockIdx.x * blockDim.x + threadIdx.x; idx < total;
         idx += gridDim.x * blockDim.x) {
        int d = idx % ED, i = (idx / ED) % NE;
        g_xs[idx] = emb_elec[i * ED + d];
    }
}

// ---------------------------------------------------------------------------
// k_msg smem (floats):
//   zsv    [0,3456)        zs[j][c], j 0..47 (38..47 zero), stride 72
//   scratch[3456,15488)
//     phase1: eiwv 8192 @3456 | xs2 3840 @11648
//     phase2: w1c tf32 [32][56] @3456 | w2c tf32 [48][72] @+1792
//             H per warp 16x52 tf32 @+1792+3456 (+w*832)
//   sb1 [15488,15536) 48 (pad 0 past 45) | sb2 [15536,15600) 64
// ---------------------------------------------------------------------------
#define MS_TOTAL_F 15600
#define MS_BYTES   (MS_TOTAL_F * 4)

__global__ void __launch_bounds__(256) k_msg(const float* __restrict__ dists,
                                             const float* __restrict__ emb_nuc,
                                             const float* __restrict__ eiw,
                                             const float* __restrict__ kw1,
                                             const float* __restrict__ kb1,
                                             const float* __restrict__ kw2,
                                             const float* __restrict__ kb2, int l) {
    extern __shared__ float sm[];
    float*  zsv     = sm;                    // 48 x stride 72
    float*  scratch = sm + 3456;
    float*  eiwv    = scratch;               // phase 1
    float*  xs2     = scratch + 8192;        // phase 1
    uint32* w1c     = reinterpret_cast<uint32*>(scratch);          // phase 2
    uint32* w2c     = w1c + 32 * 56;                               // phase 2
    uint32* Hall    = w2c + 48 * 72;                               // phase 2
    float*  sb1     = sm + 15488;
    float*  sb2     = sm + 15536;

    const int b = blockIdx.x, tid = threadIdx.x;
    const int w = tid >> 5, lane = tid & 31;
    const int g = lane >> 2, t = lane & 3;

    // ---- phase 1a: stage eiw + xs, nuclear zs, zero pad rows ----
    {
        const float* W = eiw + (size_t)l * ED * KD;
        for (int it = tid; it < ED * 32; it += 256) {
            int q = it >> 5, c = it & 31;
            sts2(eiwv + 2 * it, W[q * KD + c], W[q * KD + c + 32]);
        }
        const float* xsb = g_xs + (size_t)b * NE * ED;
        for (int it = tid; it < 15 * ED; it += 256) {
            int p = it >> 7, q = it & 127;
            sts2(xs2 + 2 * it, xsb[(2 * p) * ED + q], xsb[(2 * p + 1) * ED + q]);
        }
        for (int idx = tid; idx < NN * KD; idx += 256) {
            int n = idx >> 6, c = idx & 63;
            zsv[(NE + n) * 72 + c] = emb_nuc[n * KD + c];
        }
        for (int idx = tid; idx < 10 * 64; idx += 256) {
            int r = idx >> 6, c = idx & 63;
            zsv[(38 + r) * 72 + c] = 0.f;
        }
    }
    __syncthreads();

    // ---- phase 1b: electron zs = xs @ eiw (f32x2 over electron pairs) ----
    for (int p = w; p < 15; p += 8) {
        ull acc0 = 0ull, acc1 = 0ull;
        const float* xrow = xs2 + p * 256;
        #pragma unroll 8
        for (int q = 0; q < ED; ++q) {
            ull x2 = ldsu64(xrow + 2 * q);
            float2 wf = unpack2(ldsu64(eiwv + (q * 32 + lane) * 2));
            acc0 = ffma2(x2, dup2(wf.x), acc0);
            acc1 = ffma2(x2, dup2(wf.y), acc1);
        }
        float2 a0 = unpack2(acc0), a1 = unpack2(acc1);
        zsv[(2 * p) * 72 + lane]          = a0.x;
        zsv[(2 * p + 1) * 72 + lane]      = a0.y;
        zsv[(2 * p) * 72 + lane + 32]     = a1.x;
        zsv[(2 * p + 1) * 72 + lane + 32] = a1.y;
    }
    __syncthreads();

    // ---- phase 2a: weights -> tf32 smem (padded, conflict-free strides) ----
    {
        const float* w1 = kw1 + (size_t)l * BASIS * HK;
        const float* w2 = kw2 + (size_t)l * HK * KD;
        const float* b1 = kb1 + (size_t)l * HK;
        const float* b2 = kb2 + (size_t)l * KD;
        for (int it = tid; it < 32 * 56; it += 256) {
            int q = it / 56, c = it % 56;
            w1c[it] = f2tf((c < HK) ? w1[q * HK + c] : 0.f);
        }
        for (int it = tid; it < 48 * 72; it += 256) {
            int k = it / 72, c = it % 72;
            w2c[it] = f2tf((k < HK && c < KD) ? w2[k * KD + c] : 0.f);
        }
        if (tid < 48) sb1[tid] = (tid < HK) ? b1[tid] : 0.f;
        if (tid < 64) sb2[tid] = b2[tid];
    }
    __syncthreads();

    uint32* Hw = Hall + w * 832;   // 16 rows x stride 52

    // ---- main: warp w handles electrons i = w, w+8, ... ----
    for (int i = w; i < NE; i += 8) {
        const float* dbase = dists + ((size_t)(b * NE + i)) * NA * BASIS;
        float macc[16];
        #pragma unroll
        for (int r = 0; r < 16; ++r) macc[r] = 0.f;

        #pragma unroll
        for (int mt = 0; mt < 3; ++mt) {
            const int j0 = mt * 16 + g, j1 = j0 + 8;

            // A1 fragments straight from global (pad rows -> 0)
            uint32 A1[4][4];
            #pragma unroll
            for (int kt = 0; kt < 4; ++kt) {
                int k0 = kt * 8 + t;
                float a0 = (j0 < NA) ? __ldg(dbase + j0 * BASIS + k0) : 0.f;
                float a1 = (j1 < NA) ? __ldg(dbase + j1 * BASIS + k0) : 0.f;
                float a2 = (j0 < NA) ? __ldg(dbase + j0 * BASIS + k0 + 4) : 0.f;
                float a3 = (j1 < NA) ? __ldg(dbase + j1 * BASIS + k0 + 4) : 0.f;
                A1[kt][0] = f2tf(a0); A1[kt][1] = f2tf(a1);
                A1[kt][2] = f2tf(a2); A1[kt][3] = f2tf(a3);
            }

            // GEMM1 + ssp -> H (tf32)
            #pragma unroll
            for (int nt = 0; nt < 6; ++nt) {
                float2 bb = *reinterpret_cast<const float2*>(sb1 + nt * 8 + 2 * t);
                float d0 = bb.x, d1 = bb.y, d2 = bb.x, d3 = bb.y;
                #pragma unroll
                for (int kt = 0; kt < 4; ++kt) {
                    uint32 bf0 = w1c[(kt * 8 + t) * 56 + nt * 8 + g];
                    uint32 bf1 = w1c[(kt * 8 + t + 4) * 56 + nt * 8 + g];
                    mma8(d0, d1, d2, d3,
                         A1[kt][0], A1[kt][1], A1[kt][2], A1[kt][3], bf0, bf1);
                }
                uint2 lo = make_uint2(f2tf(ssp(d0)), f2tf(ssp(d1)));
                uint2 hi = make_uint2(f2tf(ssp(d2)), f2tf(ssp(d3)));
                *reinterpret_cast<uint2*>(Hw + g * 52 + nt * 8 + 2 * t)       = lo;
                *reinterpret_cast<uint2*>(Hw + (g + 8) * 52 + nt * 8 + 2 * t) = hi;
            }
            __syncwarp();

            // A2 fragments from H
            uint32 A2[6][4];
            #pragma unroll
            for (int kt = 0; kt < 6; ++kt) {
                A2[kt][0] = Hw[g * 52 + kt * 8 + t];
                A2[kt][1] = Hw[(g + 8) * 52 + kt * 8 + t];
                A2[kt][2] = Hw[g * 52 + kt * 8 + t + 4];
                A2[kt][3] = Hw[(g + 8) * 52 + kt * 8 + t + 4];
            }
            const float pm0 = (j0 != i) ? 1.f : 0.f;
            const float pm1 = (j1 != i) ? 1.f : 0.f;

            // GEMM2 + zs multiply + row-masked accumulate
            #pragma unroll
            for (int nt = 0; nt < 8; ++nt) {
                float2 bb = *reinterpret_cast<const float2*>(sb2 + nt * 8 + 2 * t);
                float d0 = bb.x, d1 = bb.y, d2 = bb.x, d3 = bb.y;
                #pragma unroll
                for (int kt = 0; kt < 6; ++kt) {
                    uint32 bf0 = w2c[(kt * 8 + t) * 72 + nt * 8 + g];
                    uint32 bf1 = w2c[(kt * 8 + t + 4) * 72 + nt * 8 + g];
                    mma8(d0, d1, d2, d3,
                         A2[kt][0], A2[kt][1], A2[kt][2], A2[kt][3], bf0, bf1);
                }
                float2 z0 = *reinterpret_cast<const float2*>(zsv + j0 * 72 + nt * 8 + 2 * t);
                float2 z1 = *reinterpret_cast<const float2*>(zsv + j1 * 72 + nt * 8 + 2 * t);
                macc[2 * nt]     += pm0 * d0 * z0.x + pm1 * d2 * z1.x;
                macc[2 * nt + 1] += pm0 * d1 * z0.y + pm1 * d3 * z1.y;
            }
            __syncwarp();
        }

        // butterfly reduce over the 8 row-groups (lane/4)
        #pragma unroll
        for (int r = 0; r < 16; ++r) {
            macc[r] += __shfl_xor_sync(0xffffffffu, macc[r], 4);
            macc[r] += __shfl_xor_sync(0xffffffffu, macc[r], 8);
            macc[r] += __shfl_xor_sync(0xffffffffu, macc[r], 16);
        }
        if (g == 0) {
            float* mp = g_msg + ((size_t)(b * NE + i)) * KD;
            #pragma unroll
            for (int nt = 0; nt < 8; ++nt)
                *reinterpret_cast<float2*>(mp + nt * 8 + 2 * t) =
                    make_float2(macc[2 * nt], macc[2 * nt + 1]);
        }
    }
}

// ---------------------------------------------------------------------------
// k_out (unchanged — passing R4 version)
// ---------------------------------------------------------------------------
#define VO_TOTAL_F 22144
#define VO_BYTES   (VO_TOTAL_F * 4)

__global__ void __launch_bounds__(256) k_out(const float* __restrict__ ow1,
                                             const float* __restrict__ ob1,
                                             const float* __restrict__ ow2,
                                             const float* __restrict__ ob2,
                                             int l, float* __restrict__ xs_out) {
    extern __shared__ float smo[];
    float* smsg2 = smo;
    float* sw1d  = smo + 1920;
    float* sw2d  = smo + 8064;
    float* sb1   = smo + 20352;
    float* sb2   = smo + 20480;
    float* sh2a  = smo + 20608;

    const int b = blockIdx.x, tid = threadIdx.x;
    const int w = tid >> 5, lane = tid & 31;
    const float* W1 = ow1 + (size_t)l * KD * HO;
    const float* B1 = ob1 + (size_t)l * HO;
    const float* W2 = ow2 + (size_t)l * HO * ED;
    const float* B2 = ob2 + (size_t)l * ED;

    {
        const float* mg = g_msg + (size_t)b * NE * KD;
        for (int it = tid; it < 15 * KD; it += 256) {
            int p = it >> 6, q = it & 63;
            sts2(smsg2 + 2 * it, mg[(2 * p) * KD + q], mg[(2 * p + 1) * KD + q]);
        }
        for (int it = tid; it < KD * 48; it += 256) {
            int q = it / 48, c = it % 48;
            float x = (c < HO) ? W1[q * HO + c] : 0.f;
            float y = (c + 48 < HO) ? W1[q * HO + c + 48] : 0.f;
            sts2(sw1d + 2 * it, x, y);
        }
        for (int it = tid; it < HOP * 64; it += 256) {
            int k = it >> 6, c = it & 63;
            float x = (k < HO) ? W2[k * ED + c] : 0.f;
            float y = (k < HO) ? W2[k * ED + c + 64] : 0.f;
            sts2(sw2d + 2 * it, x, y);
        }
        for (int it = tid; it < 128; it += 256) {
            sb1[it] = (it < HO) ? B1[it] : 0.f;
            sb2[it] = B2[it];
        }
    }
    __syncthreads();

    const ull bA0x = dup2(sb1[lane]);
    const ull bA0y = dup2(sb1[lane + 48]);
    const ull bA1x = dup2(sb1[lane + 32]);
    const ull bA1y = dup2(sb1[lane + 80]);
    const ull bC0 = dup2(sb2[lane]);
    const ull bC1 = dup2(sb2[lane + 32]);
    const ull bC2 = dup2(sb2[lane + 64]);
    const ull bC3 = dup2(sb2[lane + 96]);

    float* sh2 = sh2a + w * 192;

    for (int p = w; p < 15; p += 8) {
        ull A0x = bA0x, A0y = bA0y, A1x = bA1x, A1y = bA1y;
        const float* mrow = smsg2 + p * 128;
        #pragma unroll
        for (int q = 0; q < KD; ++q) {
            ull m2 = ldsu64(mrow + 2 * q);
            float2 w0 = unpack2(ldsu64(sw1d + (q * 48 + lane) * 2));
            float2 w1f = unpack2(ldsu64(sw1d + (q * 48 + lane + 32) * 2));
            A0x = ffma2(m2, dup2(w0.x), A0x);
            A0y = ffma2(m2, dup2(w0.y), A0y);
            A1x = ffma2(m2, dup2(w1f.x), A1x);
            A1y = ffma2(m2, dup2(w1f.y), A1y);
        }
        {
            float2 tv;
            tv = unpack2(A0x); sts2(sh2 + (lane) * 2,      ssp(tv.x), ssp(tv.y));
            tv = unpack2(A0y); sts2(sh2 + (lane + 48) * 2, ssp(tv.x), ssp(tv.y));
            if (lane < 16) {
                tv = unpack2(A1x); sts2(sh2 + (lane + 32) * 2, ssp(tv.x), ssp(tv.y));
                tv = unpack2(A1y); sts2(sh2 + (lane + 80) * 2, ssp(tv.x), ssp(tv.y));
            }
        }
        __syncwarp();

        ull C0 = bC0, C1 = bC1, C2 = bC2, C3 = bC3;
        #pragma unroll
        for (int k = 0; k < HOP; ++k) {
            ull h2 = ldsu64(sh2 + 2 * k);
            float2 w0 = unpack2(ldsu64(sw2d + (k * 64 + lane) * 2));
            float2 w1f = unpack2(ldsu64(sw2d + (k * 64 + lane + 32) * 2));
            C0 = ffma2(h2, dup2(w0.x), C0);
            C2 = ffma2(h2, dup2(w0.y), C2);
            C1 = ffma2(h2, dup2(w1f.x), C1);
            C3 = ffma2(h2, dup2(w1f.y), C3);
        }
        __syncwarp();

        int i0 = 2 * p, i1 = 2 * p + 1;
        size_t b0 = ((size_t)(b * NE + i0)) * ED;
        size_t b1o = ((size_t)(b * NE + i1)) * ED;
        float2 c0 = unpack2(C0), c1 = unpack2(C1), c2 = unpack2(C2), c3 = unpack2(C3);
        xs_out[b0 + lane]       = g_xs[b0 + lane]       + c0.x;
        xs_out[b0 + lane + 32]  = g_xs[b0 + lane + 32]  + c1.x;
        xs_out[b0 + lane + 64]  = g_xs[b0 + lane + 64]  + c2.x;
        xs_out[b0 + lane + 96]  = g_xs[b0 + lane + 96]  + c3.x;
        xs_out[b1o + lane]      = g_xs[b1o + lane]      + c0.y;
        xs_out[b1o + lane + 32] = g_xs[b1o + lane + 32] + c1.y;
        xs_out[b1o + lane + 64] = g_xs[b1o + lane + 64] + c2.y;
        xs_out[b1o + lane + 96] = g_xs[b1o + lane + 96] + c3.y;
    }
}

// ---------------------------------------------------------------------------
extern "C" void kernel_launch(void* const* d_in, const int* in_sizes, int n_in,
                              void* d_out, int out_size) {
    const float* dists    = (const float*)d_in[0];
    const float* emb_elec = (const float*)d_in[1];
    const float* emb_nuc  = (const float*)d_in[2];
    const float* kw1      = (const float*)d_in[3];
    const float* kb1      = (const float*)d_in[4];
    const float* kw2      = (const float*)d_in[5];
    const float* kb2      = (const float*)d_in[6];
    const float* eiw      = (const float*)d_in[7];
    const float* ow1      = (const float*)d_in[8];
    const float* ob1      = (const float*)d_in[9];
    const float* ow2      = (const float*)d_in[10];
    const float* ob2      = (const float*)d_in[11];
    float* out = (float*)d_out;

    static int configured = 0;
    if (!configured) {
        cudaFuncSetAttribute(k_msg, cudaFuncAttributeMaxDynamicSharedMemorySize, MS_BYTES);
        cudaFuncSetAttribute(k_out, cudaFuncAttributeMaxDynamicSharedMemorySize, VO_BYTES);
        configured = 1;
    }
    void* xsptr = nullptr;
    cudaGetSymbolAddress(&xsptr, g_xs);

    k_init<<<4096, 256>>>(emb_elec);
    for (int l = 0; l < NL; ++l) {
        k_msg<<<NB, 256, MS_BYTES>>>(dists, emb_nuc, eiw, kw1, kb1, kw2, kb2, l);
        float* xs_out = (l == NL - 1) ? out : (float*)xsptr;
        k_out<<<NB, 256, VO_BYTES>>>(ow1, ob1, ow2, ob2, l, xs_out);
    }
}